// round 1
// baseline (speedup 1.0000x reference)
#include <cuda_runtime.h>

// Problem constants
#define BB 32
#define AA 1024
#define DD 384
#define EE 4
#define H1C 256
#define H2C 192
#define NATOMS (BB * AA)   // 32768
#define TM 64              // atoms per tile
#define NTHREADS 256
#define MAXTILES 516       // sum ceil(c_e/64) <= 515

// Scratch (no allocations allowed)
__device__ int   g_counts[EE];
__device__ int   g_perm[EE * NATOMS];
__device__ float g_atom_energy[NATOMS];

__global__ void zero_counts_kernel() {
    if (threadIdx.x < EE) g_counts[threadIdx.x] = 0;
}

__global__ void bucket_kernel(const int* __restrict__ species) {
    int i = blockIdx.x * blockDim.x + threadIdx.x;
    if (i < NATOMS) {
        int e = species[i];
        int pos = atomicAdd(&g_counts[e], 1);
        g_perm[e * NATOMS + pos] = i;
    }
}

// Fused per-tile MLP: 64 species-uniform atoms per CTA.
//   As   [64 x 388]  full rep rows (gathered)
//   H1s  [64 x 260]  layer-1 output (NOT activated, per reference quirk)
//   Bs   [32 x 256]  streamed weight K-chunk (reused for Wh chunks + reduction buf)
__global__ __launch_bounds__(NTHREADS) void mlp_tile_kernel(
    const float* __restrict__ rep,
    const float* __restrict__ W1, const float* __restrict__ b1,
    const float* __restrict__ Wh, const float* __restrict__ bh,
    const float* __restrict__ W2, const float* __restrict__ b2)
{
    extern __shared__ float smem[];
    const int AP = DD + 4;      // 388
    const int HP = H1C + 4;     // 260
    float* As  = smem;                      // 64*388 = 24832 floats
    float* H1s = smem + TM * AP;            // 64*260 = 16640 floats
    float* Bs  = smem + TM * AP + TM * HP;  // 8192 floats

    __shared__ int prow[TM];

    const int tid = threadIdx.x;

    // Map blockIdx.x -> (species e, local tile) using bucket counts
    int c0 = g_counts[0], c1 = g_counts[1], c2 = g_counts[2], c3 = g_counts[3];
    int t0 = (c0 + TM - 1) / TM;
    int t1 = (c1 + TM - 1) / TM;
    int t2 = (c2 + TM - 1) / TM;
    int t3 = (c3 + TM - 1) / TM;
    int bid = blockIdx.x;
    int e, tloc, cnt;
    if      (bid < t0)              { e = 0; tloc = bid;                cnt = c0; }
    else if (bid < t0 + t1)         { e = 1; tloc = bid - t0;           cnt = c1; }
    else if (bid < t0 + t1 + t2)    { e = 2; tloc = bid - t0 - t1;      cnt = c2; }
    else if (bid < t0 + t1 + t2 + t3) { e = 3; tloc = bid - t0 - t1 - t2; cnt = c3; }
    else return;

    const int row0   = tloc * TM;
    const int mcount = min(TM, cnt - row0);

    if (tid < TM) {
        prow[tid] = (tid < mcount) ? g_perm[e * NATOMS + row0 + tid] : -1;
    }
    __syncthreads();

    // ---- Gather A tile: [64 x 384] fp32, float4 loads/stores ----
    for (int idx = tid; idx < TM * (DD / 4); idx += NTHREADS) {
        int m = idx / (DD / 4);
        int f = idx % (DD / 4);
        int p = prow[m];
        float4 v = make_float4(0.f, 0.f, 0.f, 0.f);
        if (p >= 0) v = ((const float4*)(rep + (long)p * DD))[f];
        ((float4*)(As + m * AP))[f] = v;
    }

    const int tx = tid & 15;   // 16 column groups
    const int ty = tid >> 4;   // 16 row groups

    // ================= Layer 1: H1s = As @ W1[e] + b1[e] =================
    float acc[4][16];
    #pragma unroll
    for (int r = 0; r < 4; r++)
        #pragma unroll
        for (int i = 0; i < 16; i++) acc[r][i] = 0.f;

    const float* W1e = W1 + (long)e * DD * H1C;
    for (int kc = 0; kc < DD; kc += 32) {
        __syncthreads();
        // load Bs[32][256] chunk of W1[e]
        for (int idx = tid; idx < 32 * (H1C / 4); idx += NTHREADS) {
            int d = idx / (H1C / 4);
            int f = idx % (H1C / 4);
            ((float4*)(Bs + d * H1C))[f] =
                ((const float4*)(W1e + (long)(kc + d) * H1C))[f];
        }
        __syncthreads();
        #pragma unroll 8
        for (int d = 0; d < 32; d++) {
            float a[4];
            #pragma unroll
            for (int r = 0; r < 4; r++) a[r] = As[(ty + 16 * r) * AP + kc + d];
            #pragma unroll
            for (int i = 0; i < 16; i++) {
                float bv = Bs[d * H1C + tx + 16 * i];
                #pragma unroll
                for (int r = 0; r < 4; r++) acc[r][i] = fmaf(a[r], bv, acc[r][i]);
            }
        }
    }
    // epilogue: add b1 (NO activation), store to H1s
    {
        const float* b1e = b1 + e * H1C;
        #pragma unroll
        for (int i = 0; i < 16; i++) {
            float bb = b1e[tx + 16 * i];
            #pragma unroll
            for (int r = 0; r < 4; r++)
                H1s[(ty + 16 * r) * HP + tx + 16 * i] = acc[r][i] + bb;
        }
    }
    __syncthreads();

    // ============ Layer 2: h2 = relu(H1s @ Wh[e] + bh[e]);  E = h2 . W2[e] ============
    float acc2[4][12];
    #pragma unroll
    for (int r = 0; r < 4; r++)
        #pragma unroll
        for (int i = 0; i < 12; i++) acc2[r][i] = 0.f;

    const float* Whe = Wh + (long)e * H1C * H2C;
    for (int kc = 0; kc < H1C; kc += 32) {
        __syncthreads();
        // load Bs[32][192] chunk of Wh[e]
        for (int idx = tid; idx < 32 * (H2C / 4); idx += NTHREADS) {
            int d = idx / (H2C / 4);
            int f = idx % (H2C / 4);
            ((float4*)(Bs + d * H2C))[f] =
                ((const float4*)(Whe + (long)(kc + d) * H2C))[f];
        }
        __syncthreads();
        #pragma unroll 8
        for (int d = 0; d < 32; d++) {
            float a[4];
            #pragma unroll
            for (int r = 0; r < 4; r++) a[r] = H1s[(ty + 16 * r) * HP + kc + d];
            #pragma unroll
            for (int i = 0; i < 12; i++) {
                float bv = Bs[d * H2C + tx + 16 * i];
                #pragma unroll
                for (int r = 0; r < 4; r++) acc2[r][i] = fmaf(a[r], bv, acc2[r][i]);
            }
        }
    }

    // fused epilogue: bias + relu + dot with W2[e], per-row partial sums
    float p[4] = {0.f, 0.f, 0.f, 0.f};
    {
        const float* bhe = bh + e * H2C;
        const float* W2e = W2 + e * H2C;
        #pragma unroll
        for (int i = 0; i < 12; i++) {
            int j = tx + 16 * i;
            float bb = bhe[j];
            float w  = W2e[j];
            #pragma unroll
            for (int r = 0; r < 4; r++) {
                float v = acc2[r][i] + bb;
                v = v > 0.f ? v : 0.f;
                p[r] = fmaf(v, w, p[r]);
            }
        }
    }

    // deterministic cross-tx reduction per atom row (reuse Bs as [64][16])
    __syncthreads();
    float* red = Bs;
    #pragma unroll
    for (int r = 0; r < 4; r++) red[(ty + 16 * r) * 16 + tx] = p[r];
    __syncthreads();
    if (tid < TM) {
        int m = tid;
        float s = 0.f;
        #pragma unroll
        for (int t = 0; t < 16; t++) s += red[m * 16 + t];
        int pidx = prow[m];
        if (pidx >= 0) g_atom_energy[pidx] = s + b2[e];
    }
}

// Deterministic per-batch reduction of 1024 atom energies
__global__ void reduce_kernel(float* __restrict__ out) {
    __shared__ float s[256];
    int b = blockIdx.x;
    int t = threadIdx.x;
    float v = 0.f;
    #pragma unroll
    for (int k = 0; k < AA; k += 256) v += g_atom_energy[b * AA + t + k];
    s[t] = v;
    __syncthreads();
    #pragma unroll
    for (int st = 128; st > 0; st >>= 1) {
        if (t < st) s[t] += s[t + st];
        __syncthreads();
    }
    if (t == 0) out[b] = s[0];
}

extern "C" void kernel_launch(void* const* d_in, const int* in_sizes, int n_in,
                              void* d_out, int out_size) {
    const float* rep     = (const float*)d_in[0];
    const int*   species = (const int*)  d_in[1];
    const float* W1      = (const float*)d_in[2];
    const float* b1      = (const float*)d_in[3];
    const float* Wh      = (const float*)d_in[4];
    const float* bh      = (const float*)d_in[5];
    const float* W2      = (const float*)d_in[6];
    const float* b2      = (const float*)d_in[7];
    float* out = (float*)d_out;

    const int smem_bytes = (TM * (DD + 4) + TM * (H1C + 4) + 32 * H1C) * sizeof(float);
    cudaFuncSetAttribute(mlp_tile_kernel,
                         cudaFuncAttributeMaxDynamicSharedMemorySize, smem_bytes);

    zero_counts_kernel<<<1, 32>>>();
    bucket_kernel<<<(NATOMS + 255) / 256, 256>>>(species);
    mlp_tile_kernel<<<MAXTILES, NTHREADS, smem_bytes>>>(rep, W1, b1, Wh, bh, W2, b2);
    reduce_kernel<<<BB, 256>>>(out);
}

// round 3
// speedup vs baseline: 3.2555x; 3.2555x over previous
#include <cuda_runtime.h>
#include <cuda_bf16.h>
#include <cstdint>

#define BB 32
#define AA 1024
#define DD 384
#define EE 4
#define H1C 256
#define H2C 192
#define NATOMS (BB*AA)
#define TM 128
#define NT 256
#define NC1 12            // 384/32 k-chunks layer1
#define NC2 8             // 256/32 k-chunks layer2
#define MAXTILES 260

// SMEM map (bytes, dynamic)
#define ABUF_OFF   0
#define ABUF_BUF   20480      // per double-buffer slot (hi+lo)
#define ABUF_SPL   10240      // 128 rows * 80B
#define BBUF_OFF   40960
#define BBUF_BUF   40960
#define BBUF_SPL   20480      // 256 rows * 80B
#define H1_OFF     0          // aliases ABUF/BBUF (phase 2)
#define H1_SPL     73728      // 8 chunks * 128 rows * 72B
#define H1_CHK     9216       // 128 * 72
#define WB_OFF     147456
#define WB_BUF     30720
#define WB_SPL     15360      // 192 rows * 80B
#define SMEM_BYTES 208896

// ---------------- device scratch ----------------
__device__ int   g_counts[EE];
__device__ int   g_perm[EE * NATOMS];
__device__ float g_atom_energy[NATOMS];
// pre-split weights, [split][e][chunk][n][40] bf16 (as ushort)
__device__ __align__(16) unsigned short g_W1b[2 * EE * NC1 * 256 * 40];
__device__ __align__(16) unsigned short g_Whb[2 * EE * NC2 * 192 * 40];
#define W1B_SPL (EE * NC1 * 256 * 40)
#define WHB_SPL (EE * NC2 * 192 * 40)

// ---------------- helpers ----------------
__device__ __forceinline__ uint32_t s2u(const void* p) {
    uint32_t a;
    asm("{ .reg .u64 t; cvta.to.shared.u64 t, %1; cvt.u32.u64 %0, t; }" : "=r"(a) : "l"(p));
    return a;
}

__device__ __forceinline__ void cp16(uint32_t dst, const void* src) {
    asm volatile("cp.async.cg.shared.global [%0], [%1], 16;" :: "r"(dst), "l"(src));
}
__device__ __forceinline__ void cp_commit() { asm volatile("cp.async.commit_group;"); }
__device__ __forceinline__ void cp_wait0()  { asm volatile("cp.async.wait_group 0;" ::: "memory"); }

__device__ __forceinline__ void split2(float x0, float x1, uint32_t& h, uint32_t& l) {
    __nv_bfloat16 h0 = __float2bfloat16_rn(x0);
    __nv_bfloat16 h1 = __float2bfloat16_rn(x1);
    float r0 = x0 - __bfloat162float(h0);
    float r1 = x1 - __bfloat162float(h1);
    __nv_bfloat16 l0 = __float2bfloat16_rn(r0);
    __nv_bfloat16 l1 = __float2bfloat16_rn(r1);
    h = (uint32_t)__bfloat16_as_ushort(h0) | ((uint32_t)__bfloat16_as_ushort(h1) << 16);
    l = (uint32_t)__bfloat16_as_ushort(l0) | ((uint32_t)__bfloat16_as_ushort(l1) << 16);
}

__device__ __forceinline__ void split1(float x, unsigned short& h, unsigned short& l) {
    __nv_bfloat16 hb = __float2bfloat16_rn(x);
    float r = x - __bfloat162float(hb);
    __nv_bfloat16 lb = __float2bfloat16_rn(r);
    h = __bfloat16_as_ushort(hb);
    l = __bfloat16_as_ushort(lb);
}

__device__ __forceinline__ void mma_bf16(float* d,
        uint32_t a0, uint32_t a1, uint32_t a2, uint32_t a3,
        uint32_t b0, uint32_t b1) {
    asm volatile(
        "mma.sync.aligned.m16n8k16.row.col.f32.bf16.bf16.f32 "
        "{%0,%1,%2,%3}, {%4,%5,%6,%7}, {%8,%9}, {%0,%1,%2,%3};"
        : "+f"(d[0]), "+f"(d[1]), "+f"(d[2]), "+f"(d[3])
        : "r"(a0), "r"(a1), "r"(a2), "r"(a3), "r"(b0), "r"(b1));
}

// ---------------- setup kernels ----------------
__global__ void zero_counts_kernel() {
    if (threadIdx.x < EE) g_counts[threadIdx.x] = 0;
}

__global__ void bucket_kernel(const int* __restrict__ species) {
    int i = blockIdx.x * blockDim.x + threadIdx.x;
    if (i < NATOMS) {
        int e = species[i];
        int pos = atomicAdd(&g_counts[e], 1);
        g_perm[e * NATOMS + pos] = i;
    }
}

// split weights to bf16 hi/lo, layout [split][e][chunk][n][40]
__global__ void prep_weights_kernel(const float* __restrict__ W1,
                                    const float* __restrict__ Wh) {
    const int TOT1 = EE * DD * H1C;     // 393216
    const int TOT2 = EE * H1C * H2C;    // 196608
    int idx = blockIdx.x * blockDim.x + threadIdx.x;
    if (idx < TOT1) {
        int e = idx / (DD * H1C);
        int rem = idx % (DD * H1C);
        int k = rem / H1C, n = rem % H1C;
        unsigned short h, l;
        split1(W1[idx], h, l);
        int chunk = k >> 5, kin = k & 31;
        size_t dst = (((size_t)e * NC1 + chunk) * 256 + n) * 40 + kin;
        g_W1b[dst] = h;
        g_W1b[W1B_SPL + dst] = l;
    } else if (idx < TOT1 + TOT2) {
        int j = idx - TOT1;
        int e = j / (H1C * H2C);
        int rem = j % (H1C * H2C);
        int k = rem / H2C, n = rem % H2C;
        unsigned short h, l;
        split1(Wh[j], h, l);
        int chunk = k >> 5, kin = k & 31;
        size_t dst = (((size_t)e * NC2 + chunk) * 192 + n) * 40 + kin;
        g_Whb[dst] = h;
        g_Whb[WHB_SPL + dst] = l;
    }
}

// ---------------- fused 2-layer MLP via mma.sync bf16 (2-split, 3 products) ----------------
__global__ void __launch_bounds__(NT, 1) fused_mlp(
    const float* __restrict__ rep,
    const float* __restrict__ b1, const float* __restrict__ bh,
    const float* __restrict__ W2, const float* __restrict__ b2)
{
    extern __shared__ __align__(16) char dsm[];
    __shared__ int   prow[TM];
    __shared__ float b1s[H1C];
    __shared__ float bhs[H2C];
    __shared__ float w2s[H2C];
    __shared__ float red[TM][2];

    const int tid  = threadIdx.x;
    const int w    = tid >> 5;
    const int lane = tid & 31;
    const int g    = lane >> 2;
    const int t    = lane & 3;
    const int wm   = w >> 1;       // 0..3
    const int wn   = w & 1;        // 0..1
    const int R0   = wm * 32;

    // map blockIdx -> (species, tile)
    int c0 = g_counts[0], c1 = g_counts[1], c2 = g_counts[2], c3 = g_counts[3];
    int t0 = (c0 + TM - 1) / TM, t1 = (c1 + TM - 1) / TM;
    int t2 = (c2 + TM - 1) / TM, t3 = (c3 + TM - 1) / TM;
    int bid = blockIdx.x, e, tloc, cnt;
    if      (bid < t0)                { e = 0; tloc = bid;                cnt = c0; }
    else if (bid < t0 + t1)           { e = 1; tloc = bid - t0;           cnt = c1; }
    else if (bid < t0 + t1 + t2)      { e = 2; tloc = bid - t0 - t1;      cnt = c2; }
    else if (bid < t0 + t1 + t2 + t3) { e = 3; tloc = bid - t0 - t1 - t2; cnt = c3; }
    else return;

    const int row0   = tloc * TM;
    const int mcount = min(TM, cnt - row0);
    if (tid < TM)
        prow[tid] = (tid < mcount) ? g_perm[e * NATOMS + row0 + tid] : -1;
    if (tid < H1C) b1s[tid] = b1[e * H1C + tid];
    if (tid < H2C) { bhs[tid] = bh[e * H2C + tid]; w2s[tid] = W2[e * H2C + tid]; }
    __syncthreads();

    const uint32_t sb = s2u(dsm);

    // ================== LAYER 1: D1[128x256] = A @ W1[e]^T-ish ==================
    {
        const int C0 = wn * 128;
        float acc[2][16][4];
        #pragma unroll
        for (int mt = 0; mt < 2; mt++)
            #pragma unroll
            for (int nt = 0; nt < 16; nt++)
                #pragma unroll
                for (int q = 0; q < 4; q++) acc[mt][nt][q] = 0.f;

        const char* w1h_g = (const char*)(g_W1b + ((size_t)e * NC1) * 256 * 40);
        const char* w1l_g = (const char*)(g_W1b + ((size_t)(W1B_SPL) + (size_t)e * NC1 * 256 * 40));

        float4 va[4];
        // --- preamble: A(0) regs -> abuf0; cp.async B(0) -> bbuf0 ---
        {
            #pragma unroll
            for (int j = 0; j < 4; j++) {
                int item = tid + j * NT;
                int r = item >> 3, f = item & 7;
                int p = prow[r];
                va[j] = (p >= 0) ? __ldg((const float4*)(rep + (size_t)p * DD + 0 * 32 + f * 4))
                                 : make_float4(0.f, 0.f, 0.f, 0.f);
            }
            // B(0)
            #pragma unroll 1
            for (int i = tid; i < 1280; i += NT) {
                cp16(sb + BBUF_OFF + i * 16,               w1h_g + (size_t)0 * 20480 + i * 16);
                cp16(sb + BBUF_OFF + BBUF_SPL + i * 16,    w1l_g + (size_t)0 * 20480 + i * 16);
            }
            cp_commit();
            // cvt/store A(0) -> abuf0
            char* Ah = dsm + ABUF_OFF;
            char* Al = Ah + ABUF_SPL;
            #pragma unroll
            for (int j = 0; j < 4; j++) {
                int item = tid + j * NT;
                int r = item >> 3, f = item & 7;
                uint32_t h0, l0, h1, l1;
                split2(va[j].x, va[j].y, h0, l0);
                split2(va[j].z, va[j].w, h1, l1);
                *(uint2*)(Ah + r * 80 + f * 8) = make_uint2(h0, h1);
                *(uint2*)(Al + r * 80 + f * 8) = make_uint2(l0, l1);
            }
            // A(1) regs
            #pragma unroll
            for (int j = 0; j < 4; j++) {
                int item = tid + j * NT;
                int r = item >> 3, f = item & 7;
                int p = prow[r];
                va[j] = (p >= 0) ? __ldg((const float4*)(rep + (size_t)p * DD + 1 * 32 + f * 4))
                                 : make_float4(0.f, 0.f, 0.f, 0.f);
            }
            cp_wait0();
            __syncthreads();
        }

        for (int kc = 0; kc < NC1; kc++) {
            const int buf = kc & 1;
            if (kc + 1 < NC1) {
                const int nb = buf ^ 1;
                #pragma unroll 1
                for (int i = tid; i < 1280; i += NT) {
                    cp16(sb + BBUF_OFF + nb * BBUF_BUF + i * 16,
                         w1h_g + (size_t)(kc + 1) * 20480 + i * 16);
                    cp16(sb + BBUF_OFF + nb * BBUF_BUF + BBUF_SPL + i * 16,
                         w1l_g + (size_t)(kc + 1) * 20480 + i * 16);
                }
                cp_commit();
            }
            // MMA on chunk kc
            {
                const char* Ah = dsm + ABUF_OFF + buf * ABUF_BUF;
                const char* Al = Ah + ABUF_SPL;
                const char* Bh = dsm + BBUF_OFF + buf * BBUF_BUF;
                const char* Bl = Bh + BBUF_SPL;
                #pragma unroll
                for (int kk = 0; kk < 2; kk++) {
                    const int kb = kk * 16;
                    uint32_t ah[2][4], al[2][4];
                    #pragma unroll
                    for (int mt = 0; mt < 2; mt++) {
                        int r0 = R0 + mt * 16 + g;
                        ah[mt][0] = *(const uint32_t*)(Ah + r0 * 80 + (kb + 2 * t) * 2);
                        ah[mt][1] = *(const uint32_t*)(Ah + (r0 + 8) * 80 + (kb + 2 * t) * 2);
                        ah[mt][2] = *(const uint32_t*)(Ah + r0 * 80 + (kb + 2 * t + 8) * 2);
                        ah[mt][3] = *(const uint32_t*)(Ah + (r0 + 8) * 80 + (kb + 2 * t + 8) * 2);
                        al[mt][0] = *(const uint32_t*)(Al + r0 * 80 + (kb + 2 * t) * 2);
                        al[mt][1] = *(const uint32_t*)(Al + (r0 + 8) * 80 + (kb + 2 * t) * 2);
                        al[mt][2] = *(const uint32_t*)(Al + r0 * 80 + (kb + 2 * t + 8) * 2);
                        al[mt][3] = *(const uint32_t*)(Al + (r0 + 8) * 80 + (kb + 2 * t + 8) * 2);
                    }
                    #pragma unroll
                    for (int nt = 0; nt < 16; nt++) {
                        int n0 = C0 + nt * 8 + g;
                        uint32_t bh0 = *(const uint32_t*)(Bh + n0 * 80 + (kb + 2 * t) * 2);
                        uint32_t bh1 = *(const uint32_t*)(Bh + n0 * 80 + (kb + 2 * t + 8) * 2);
                        uint32_t bl0 = *(const uint32_t*)(Bl + n0 * 80 + (kb + 2 * t) * 2);
                        uint32_t bl1 = *(const uint32_t*)(Bl + n0 * 80 + (kb + 2 * t + 8) * 2);
                        #pragma unroll
                        for (int mt = 0; mt < 2; mt++) {
                            mma_bf16(acc[mt][nt], ah[mt][0], ah[mt][1], ah[mt][2], ah[mt][3], bh0, bh1);
                            mma_bf16(acc[mt][nt], ah[mt][0], ah[mt][1], ah[mt][2], ah[mt][3], bl0, bl1);
                            mma_bf16(acc[mt][nt], al[mt][0], al[mt][1], al[mt][2], al[mt][3], bh0, bh1);
                        }
                    }
                }
            }
            if (kc + 1 < NC1) {
                // cvt/store A(kc+1), prefetch A(kc+2)
                char* Ah = dsm + ABUF_OFF + (buf ^ 1) * ABUF_BUF;
                char* Al = Ah + ABUF_SPL;
                #pragma unroll
                for (int j = 0; j < 4; j++) {
                    int item = tid + j * NT;
                    int r = item >> 3, f = item & 7;
                    uint32_t h0, l0, h1, l1;
                    split2(va[j].x, va[j].y, h0, l0);
                    split2(va[j].z, va[j].w, h1, l1);
                    *(uint2*)(Ah + r * 80 + f * 8) = make_uint2(h0, h1);
                    *(uint2*)(Al + r * 80 + f * 8) = make_uint2(l0, l1);
                }
                if (kc + 2 < NC1) {
                    #pragma unroll
                    for (int j = 0; j < 4; j++) {
                        int item = tid + j * NT;
                        int r = item >> 3, f = item & 7;
                        int p = prow[r];
                        va[j] = (p >= 0)
                              ? __ldg((const float4*)(rep + (size_t)p * DD + (kc + 2) * 32 + f * 4))
                              : make_float4(0.f, 0.f, 0.f, 0.f);
                    }
                }
                cp_wait0();
            }
            __syncthreads();
        }

        // ---- start layer-2 weight prefetch (WB region is disjoint from H1) ----
        {
            const char* whh_g = (const char*)(g_Whb + ((size_t)e * NC2) * 192 * 40);
            const char* whl_g = (const char*)(g_Whb + ((size_t)WHB_SPL + (size_t)e * NC2 * 192 * 40));
            #pragma unroll 1
            for (int i = tid; i < 960; i += NT) {
                cp16(sb + WB_OFF + i * 16,           whh_g + i * 16);
                cp16(sb + WB_OFF + WB_SPL + i * 16,  whl_g + i * 16);
            }
            cp_commit();
        }

        // ---- write H1 = D1 + b1 (NO relu — reference quirk) into chunked smem ----
        {
            char* Hh = dsm + H1_OFF;
            char* Hl = Hh + H1_SPL;
            #pragma unroll
            for (int mt = 0; mt < 2; mt++) {
                #pragma unroll
                for (int nt = 0; nt < 16; nt++) {
                    int c0i = C0 + nt * 8 + 2 * t;
                    int chunk = c0i >> 5, kin = c0i & 31;
                    int r0 = R0 + mt * 16 + g;
                    float v0 = acc[mt][nt][0] + b1s[c0i];
                    float v1 = acc[mt][nt][1] + b1s[c0i + 1];
                    float v2 = acc[mt][nt][2] + b1s[c0i];
                    float v3 = acc[mt][nt][3] + b1s[c0i + 1];
                    uint32_t h, l;
                    split2(v0, v1, h, l);
                    *(uint32_t*)(Hh + chunk * H1_CHK + r0 * 72 + kin * 2) = h;
                    *(uint32_t*)(Hl + chunk * H1_CHK + r0 * 72 + kin * 2) = l;
                    split2(v2, v3, h, l);
                    *(uint32_t*)(Hh + chunk * H1_CHK + (r0 + 8) * 72 + kin * 2) = h;
                    *(uint32_t*)(Hl + chunk * H1_CHK + (r0 + 8) * 72 + kin * 2) = l;
                }
            }
        }
        cp_wait0();
        __syncthreads();
    }

    // ================== LAYER 2: D2[128x192] = H1 @ Wh[e] ==================
    {
        const int C0 = wn * 96;
        float acc[2][12][4];
        #pragma unroll
        for (int mt = 0; mt < 2; mt++)
            #pragma unroll
            for (int nt = 0; nt < 12; nt++)
                #pragma unroll
                for (int q = 0; q < 4; q++) acc[mt][nt][q] = 0.f;

        const char* whh_g = (const char*)(g_Whb + ((size_t)e * NC2) * 192 * 40);
        const char* whl_g = (const char*)(g_Whb + ((size_t)WHB_SPL + (size_t)e * NC2 * 192 * 40));
        const char* Hh = dsm + H1_OFF;
        const char* Hl = Hh + H1_SPL;

        for (int kc = 0; kc < NC2; kc++) {
            const int buf = kc & 1;
            if (kc + 1 < NC2) {
                const int nb = buf ^ 1;
                #pragma unroll 1
                for (int i = tid; i < 960; i += NT) {
                    cp16(sb + WB_OFF + nb * WB_BUF + i * 16,
                         whh_g + (size_t)(kc + 1) * 15360 + i * 16);
                    cp16(sb + WB_OFF + nb * WB_BUF + WB_SPL + i * 16,
                         whl_g + (size_t)(kc + 1) * 15360 + i * 16);
                }
                cp_commit();
            }
            {
                const char* Bh = dsm + WB_OFF + buf * WB_BUF;
                const char* Bl = Bh + WB_SPL;
                #pragma unroll
                for (int kk = 0; kk < 2; kk++) {
                    const int kb = kk * 16;
                    uint32_t ah[2][4], al[2][4];
                    #pragma unroll
                    for (int mt = 0; mt < 2; mt++) {
                        int r0 = R0 + mt * 16 + g;
                        const char* HhC = Hh + kc * H1_CHK;
                        const char* HlC = Hl + kc * H1_CHK;
                        ah[mt][0] = *(const uint32_t*)(HhC + r0 * 72 + (kb + 2 * t) * 2);
                        ah[mt][1] = *(const uint32_t*)(HhC + (r0 + 8) * 72 + (kb + 2 * t) * 2);
                        ah[mt][2] = *(const uint32_t*)(HhC + r0 * 72 + (kb + 2 * t + 8) * 2);
                        ah[mt][3] = *(const uint32_t*)(HhC + (r0 + 8) * 72 + (kb + 2 * t + 8) * 2);
                        al[mt][0] = *(const uint32_t*)(HlC + r0 * 72 + (kb + 2 * t) * 2);
                        al[mt][1] = *(const uint32_t*)(HlC + (r0 + 8) * 72 + (kb + 2 * t) * 2);
                        al[mt][2] = *(const uint32_t*)(HlC + r0 * 72 + (kb + 2 * t + 8) * 2);
                        al[mt][3] = *(const uint32_t*)(HlC + (r0 + 8) * 72 + (kb + 2 * t + 8) * 2);
                    }
                    #pragma unroll
                    for (int nt = 0; nt < 12; nt++) {
                        int n0 = C0 + nt * 8 + g;
                        uint32_t bh0 = *(const uint32_t*)(Bh + n0 * 80 + (kb + 2 * t) * 2);
                        uint32_t bh1 = *(const uint32_t*)(Bh + n0 * 80 + (kb + 2 * t + 8) * 2);
                        uint32_t bl0 = *(const uint32_t*)(Bl + n0 * 80 + (kb + 2 * t) * 2);
                        uint32_t bl1 = *(const uint32_t*)(Bl + n0 * 80 + (kb + 2 * t + 8) * 2);
                        #pragma unroll
                        for (int mt = 0; mt < 2; mt++) {
                            mma_bf16(acc[mt][nt], ah[mt][0], ah[mt][1], ah[mt][2], ah[mt][3], bh0, bh1);
                            mma_bf16(acc[mt][nt], ah[mt][0], ah[mt][1], ah[mt][2], ah[mt][3], bl0, bl1);
                            mma_bf16(acc[mt][nt], al[mt][0], al[mt][1], al[mt][2], al[mt][3], bh0, bh1);
                        }
                    }
                }
            }
            if (kc + 1 < NC2) cp_wait0();
            __syncthreads();
        }

        // ---- fused epilogue: e = relu(D2 + bh) . W2 ----
        float p[2][2] = {{0.f, 0.f}, {0.f, 0.f}};
        #pragma unroll
        for (int mt = 0; mt < 2; mt++) {
            #pragma unroll
            for (int nt = 0; nt < 12; nt++) {
                int c0i = C0 + nt * 8 + 2 * t;
                float bb0 = bhs[c0i],     w0 = w2s[c0i];
                float bb1 = bhs[c0i + 1], w1v = w2s[c0i + 1];
                float v;
                v = acc[mt][nt][0] + bb0; v = v > 0.f ? v : 0.f; p[mt][0] = fmaf(v, w0, p[mt][0]);
                v = acc[mt][nt][1] + bb1; v = v > 0.f ? v : 0.f; p[mt][0] = fmaf(v, w1v, p[mt][0]);
                v = acc[mt][nt][2] + bb0; v = v > 0.f ? v : 0.f; p[mt][1] = fmaf(v, w0, p[mt][1]);
                v = acc[mt][nt][3] + bb1; v = v > 0.f ? v : 0.f; p[mt][1] = fmaf(v, w1v, p[mt][1]);
            }
        }
        // reduce across the 4 lanes of each row group (t dimension)
        #pragma unroll
        for (int mt = 0; mt < 2; mt++) {
            #pragma unroll
            for (int h = 0; h < 2; h++) {
                p[mt][h] += __shfl_xor_sync(0xffffffffu, p[mt][h], 1);
                p[mt][h] += __shfl_xor_sync(0xffffffffu, p[mt][h], 2);
            }
        }
        if (t == 0) {
            #pragma unroll
            for (int mt = 0; mt < 2; mt++) {
                red[R0 + mt * 16 + g][wn]     = p[mt][0];
                red[R0 + mt * 16 + g + 8][wn] = p[mt][1];
            }
        }
        __syncthreads();
        if (tid < TM) {
            int pr = prow[tid];
            if (pr >= 0)
                g_atom_energy[pr] = red[tid][0] + red[tid][1] + b2[e];
        }
    }
}

// ---------------- deterministic per-batch reduction ----------------
__global__ void reduce_kernel(float* __restrict__ out) {
    __shared__ float s[256];
    int b = blockIdx.x, t = threadIdx.x;
    float v = 0.f;
    #pragma unroll
    for (int k = 0; k < AA; k += 256) v += g_atom_energy[b * AA + t + k];
    s[t] = v;
    __syncthreads();
    #pragma unroll
    for (int st = 128; st > 0; st >>= 1) {
        if (t < st) s[t] += s[t + st];
        __syncthreads();
    }
    if (t == 0) out[b] = s[0];
}

extern "C" void kernel_launch(void* const* d_in, const int* in_sizes, int n_in,
                              void* d_out, int out_size) {
    const float* rep     = (const float*)d_in[0];
    const int*   species = (const int*)  d_in[1];
    const float* W1      = (const float*)d_in[2];
    const float* b1      = (const float*)d_in[3];
    const float* Wh      = (const float*)d_in[4];
    const float* bh      = (const float*)d_in[5];
    const float* W2      = (const float*)d_in[6];
    const float* b2      = (const float*)d_in[7];
    float* out = (float*)d_out;

    cudaFuncSetAttribute(fused_mlp,
                         cudaFuncAttributeMaxDynamicSharedMemorySize, SMEM_BYTES);

    zero_counts_kernel<<<1, 32>>>();
    bucket_kernel<<<(NATOMS + 255) / 256, 256>>>(species);
    const int PREP = EE * DD * H1C + EE * H1C * H2C;
    prep_weights_kernel<<<(PREP + 255) / 256, 256>>>(W1, Wh);
    fused_mlp<<<MAXTILES, NT, SMEM_BYTES>>>(rep, b1, bh, W2, b2);
    reduce_kernel<<<BB, 256>>>(out);
}

// round 4
// speedup vs baseline: 3.5049x; 1.0766x over previous
#include <cuda_runtime.h>
#include <cuda_bf16.h>
#include <cstdint>

#define BB 32
#define AA 1024
#define DD 384
#define EE 4
#define H1C 256
#define H2C 192
#define NATOMS (BB*AA)
#define TM 64
#define NT 256
#define NC1 12
#define NC2 8
#define MAXTILES 516

// ---- dynamic SMEM byte map (per CTA) ----
#define AB_OFF 0
#define AB_BUF 10240       // per buffer: hi 5120 (64 rows x 80B) + lo 5120
#define AB_SPL 5120
#define BBF_OFF 20480
#define BBF_BUF 40960      // per buffer: hi 20480 (256 rows x 80B) + lo
#define BBF_SPL 20480
#define H1_LO_OFF 32768    // H1: hi at 0, lo at 32768 (8 chunks x 64 rows x 64B)
#define H1_CHK 4096
#define WB_OFF 65536       // single buffer: hi 15360 (192 rows x 80B) + lo
#define WB_SPL 15360
#define DSMEM 102400

#define W1CHUNK 20480
#define WHCHUNK 15360
#define W1LO ((size_t)EE * NC1 * W1CHUNK)   // 983040 bytes
#define WHLO ((size_t)EE * NC2 * WHCHUNK)   // 491520 bytes

// ---------------- device scratch ----------------
__device__ int   g_counts[EE];
__device__ int   g_perm[EE * NATOMS];
__device__ float g_atom_energy[NATOMS];
// pre-split weights: [split][e][chunk][n][40] ushorts (80B rows, 8-pad)
__device__ __align__(16) unsigned short g_W1b[2 * EE * NC1 * 256 * 40];
__device__ __align__(16) unsigned short g_Whb[2 * EE * NC2 * 192 * 40];

// ---------------- helpers ----------------
__device__ __forceinline__ uint32_t s2u(const void* p) {
    uint32_t a;
    asm("{ .reg .u64 t; cvta.to.shared.u64 t, %1; cvt.u32.u64 %0, t; }" : "=r"(a) : "l"(p));
    return a;
}
__device__ __forceinline__ void cp16(uint32_t dst, const void* src) {
    asm volatile("cp.async.cg.shared.global [%0], [%1], 16;" :: "r"(dst), "l"(src));
}
__device__ __forceinline__ void cp_commit() { asm volatile("cp.async.commit_group;"); }
__device__ __forceinline__ void cp_wait0()  { asm volatile("cp.async.wait_group 0;" ::: "memory"); }

__device__ __forceinline__ void split2(float x0, float x1, uint32_t& h, uint32_t& l) {
    __nv_bfloat16 h0 = __float2bfloat16_rn(x0);
    __nv_bfloat16 h1 = __float2bfloat16_rn(x1);
    float r0 = x0 - __bfloat162float(h0);
    float r1 = x1 - __bfloat162float(h1);
    __nv_bfloat16 l0 = __float2bfloat16_rn(r0);
    __nv_bfloat16 l1 = __float2bfloat16_rn(r1);
    h = (uint32_t)__bfloat16_as_ushort(h0) | ((uint32_t)__bfloat16_as_ushort(h1) << 16);
    l = (uint32_t)__bfloat16_as_ushort(l0) | ((uint32_t)__bfloat16_as_ushort(l1) << 16);
}

__device__ __forceinline__ void mma_bf16(float* d,
        uint32_t a0, uint32_t a1, uint32_t a2, uint32_t a3,
        uint32_t b0, uint32_t b1) {
    asm volatile(
        "mma.sync.aligned.m16n8k16.row.col.f32.bf16.bf16.f32 "
        "{%0,%1,%2,%3}, {%4,%5,%6,%7}, {%8,%9}, {%0,%1,%2,%3};"
        : "+f"(d[0]), "+f"(d[1]), "+f"(d[2]), "+f"(d[3])
        : "r"(a0), "r"(a1), "r"(a2), "r"(a3), "r"(b0), "r"(b1));
}

__device__ __forceinline__ void ldm4(uint32_t* r, uint32_t addr) {
    asm volatile("ldmatrix.sync.aligned.m8n8.x4.shared.b16 {%0,%1,%2,%3}, [%4];"
        : "=r"(r[0]), "=r"(r[1]), "=r"(r[2]), "=r"(r[3]) : "r"(addr));
}

// ---------------- setup kernels ----------------
__global__ void zero_counts_kernel() {
    if (threadIdx.x < EE) g_counts[threadIdx.x] = 0;
}

__global__ void bucket_kernel(const int* __restrict__ species) {
    int i = blockIdx.x * blockDim.x + threadIdx.x;
    if (i < NATOMS) {
        int e = species[i];
        int pos = atomicAdd(&g_counts[e], 1);
        g_perm[e * NATOMS + pos] = i;
    }
}

// one thread per (e, chunk, n): coalesced reads, uint4 stores
__global__ void prep_weights_kernel(const float* __restrict__ W1,
                                    const float* __restrict__ Wh) {
    const int T1 = EE * NC1 * 256;   // 12288
    const int T2 = EE * NC2 * 192;   // 6144
    int idx = blockIdx.x * blockDim.x + threadIdx.x;
    if (idx < T1) {
        int e = idx / (NC1 * 256);
        int r = idx % (NC1 * 256);
        int chunk = r / 256, n = r % 256;
        const float* src = W1 + ((size_t)e * DD + chunk * 32) * H1C + n;
        uint4* dh = (uint4*)(g_W1b + (size_t)idx * 40);
        uint4* dl = (uint4*)((char*)dh + W1LO);
        #pragma unroll
        for (int q = 0; q < 4; q++) {
            uint32_t ph[4], pl[4];
            #pragma unroll
            for (int j = 0; j < 4; j++) {
                float w0 = src[(size_t)(q * 8 + 2 * j) * H1C];
                float w1 = src[(size_t)(q * 8 + 2 * j + 1) * H1C];
                split2(w0, w1, ph[j], pl[j]);
            }
            dh[q] = make_uint4(ph[0], ph[1], ph[2], ph[3]);
            dl[q] = make_uint4(pl[0], pl[1], pl[2], pl[3]);
        }
        dh[4] = make_uint4(0, 0, 0, 0);
        dl[4] = make_uint4(0, 0, 0, 0);
    } else if (idx < T1 + T2) {
        int i2 = idx - T1;
        int e = i2 / (NC2 * 192);
        int r = i2 % (NC2 * 192);
        int chunk = r / 192, n = r % 192;
        const float* src = Wh + ((size_t)e * H1C + chunk * 32) * H2C + n;
        uint4* dh = (uint4*)(g_Whb + (size_t)i2 * 40);
        uint4* dl = (uint4*)((char*)dh + WHLO);
        #pragma unroll
        for (int q = 0; q < 4; q++) {
            uint32_t ph[4], pl[4];
            #pragma unroll
            for (int j = 0; j < 4; j++) {
                float w0 = src[(size_t)(q * 8 + 2 * j) * H2C];
                float w1 = src[(size_t)(q * 8 + 2 * j + 1) * H2C];
                split2(w0, w1, ph[j], pl[j]);
            }
            dh[q] = make_uint4(ph[0], ph[1], ph[2], ph[3]);
            dl[q] = make_uint4(pl[0], pl[1], pl[2], pl[3]);
        }
        dh[4] = make_uint4(0, 0, 0, 0);
        dl[4] = make_uint4(0, 0, 0, 0);
    }
}

// ---------------- fused 2-layer MLP (bf16 2-split, 3-product, ldmatrix) ----------------
__global__ void __launch_bounds__(NT, 2) fused_mlp(
    const float* __restrict__ rep,
    const float* __restrict__ b1, const float* __restrict__ bh,
    const float* __restrict__ W2, const float* __restrict__ b2)
{
    extern __shared__ __align__(16) char dsm[];
    __shared__ int   prow[TM];
    __shared__ float b1s[H1C];
    __shared__ float bhs[H2C];
    __shared__ float w2s[H2C];
    __shared__ float red[TM][2];

    const int tid  = threadIdx.x;
    const int w    = tid >> 5;
    const int lane = tid & 31;
    const int g    = lane >> 2;
    const int t    = lane & 3;
    const int wm   = w >> 1;       // 0..3 -> 16-row slab
    const int wn   = w & 1;        // 0..1 -> N half
    const int R0   = wm * 16;
    const int llow = lane & 15;
    const int ahi16 = (lane >> 4) << 4;

    // map blockIdx -> (species, tile)
    int c0 = g_counts[0], c1 = g_counts[1], c2 = g_counts[2], c3 = g_counts[3];
    int t0 = (c0 + TM - 1) / TM, t1 = (c1 + TM - 1) / TM;
    int t2 = (c2 + TM - 1) / TM, t3 = (c3 + TM - 1) / TM;
    int bid = blockIdx.x, e, tloc, cnt;
    if      (bid < t0)                { e = 0; tloc = bid;                cnt = c0; }
    else if (bid < t0 + t1)           { e = 1; tloc = bid - t0;           cnt = c1; }
    else if (bid < t0 + t1 + t2)      { e = 2; tloc = bid - t0 - t1;      cnt = c2; }
    else if (bid < t0 + t1 + t2 + t3) { e = 3; tloc = bid - t0 - t1 - t2; cnt = c3; }
    else return;

    const int row0   = tloc * TM;
    const int mcount = min(TM, cnt - row0);
    if (tid < TM)
        prow[tid] = (tid < mcount) ? g_perm[e * NATOMS + row0 + tid] : -1;
    b1s[tid] = b1[e * H1C + tid];
    if (tid < H2C) { bhs[tid] = bh[e * H2C + tid]; w2s[tid] = W2[e * H2C + tid]; }
    __syncthreads();

    const uint32_t sb = s2u(dsm);
    const char* w1g = (const char*)g_W1b + (size_t)e * NC1 * W1CHUNK;
    const char* whg = (const char*)g_Whb + (size_t)e * NC2 * WHCHUNK;

    // lane-dependent fragment address offsets
    const uint32_t aoff  = (uint32_t)((R0 + llow) * 80 + ahi16);
    const uint32_t boff1 = (uint32_t)((wn * 128 + (lane & 7) + ((lane >> 4) << 3)) * 80
                                      + (((lane >> 3) & 1) << 4));
    const uint32_t boff2 = (uint32_t)((wn * 96 + (lane & 7) + ((lane >> 4) << 3)) * 80
                                      + (((lane >> 3) & 1) << 4));
    // H1 (64B rows, 16B-block XOR swizzle by row&3)
    const uint32_t h1row = (uint32_t)(R0 + llow);
    const uint32_t h1sw  = (h1row & 3) << 4;
    const uint32_t h1off = h1row * 64;

    // ================== LAYER 1: D1[64x256] = A @ W1[e]^T ==================
    float acc[16][4];
    #pragma unroll
    for (int nt = 0; nt < 16; nt++)
        #pragma unroll
        for (int q = 0; q < 4; q++) acc[nt][q] = 0.f;

    float4 va[2];
    // preamble: A(0) -> abuf0, cp.async B(0) -> bbuf0, va = A(1)
    {
        #pragma unroll
        for (int j = 0; j < 2; j++) {
            int item = tid + j * NT;
            int r = item >> 3, f = item & 7;
            int p = prow[r];
            va[j] = (p >= 0) ? __ldg((const float4*)(rep + (size_t)p * DD + f * 4))
                             : make_float4(0.f, 0.f, 0.f, 0.f);
        }
        #pragma unroll 1
        for (int i = tid; i < 1280; i += NT) {
            cp16(sb + BBF_OFF + i * 16,           w1g + i * 16);
            cp16(sb + BBF_OFF + BBF_SPL + i * 16, w1g + W1LO + i * 16);
        }
        cp_commit();
        char* Ah = dsm + AB_OFF;
        #pragma unroll
        for (int j = 0; j < 2; j++) {
            int item = tid + j * NT;
            int r = item >> 3, f = item & 7;
            uint32_t h0, l0, h1, l1;
            split2(va[j].x, va[j].y, h0, l0);
            split2(va[j].z, va[j].w, h1, l1);
            *(uint2*)(Ah + r * 80 + f * 8) = make_uint2(h0, h1);
            *(uint2*)(Ah + AB_SPL + r * 80 + f * 8) = make_uint2(l0, l1);
        }
        #pragma unroll
        for (int j = 0; j < 2; j++) {
            int item = tid + j * NT;
            int r = item >> 3, f = item & 7;
            int p = prow[r];
            va[j] = (p >= 0) ? __ldg((const float4*)(rep + (size_t)p * DD + 32 + f * 4))
                             : make_float4(0.f, 0.f, 0.f, 0.f);
        }
        cp_wait0();
        __syncthreads();
    }

    for (int kc = 0; kc < NC1; kc++) {
        const int buf = kc & 1;
        if (kc + 1 < NC1) {
            const int nb = buf ^ 1;
            const char* srcH = w1g + (size_t)(kc + 1) * W1CHUNK;
            #pragma unroll 1
            for (int i = tid; i < 1280; i += NT) {
                cp16(sb + BBF_OFF + nb * BBF_BUF + i * 16,           srcH + i * 16);
                cp16(sb + BBF_OFF + nb * BBF_BUF + BBF_SPL + i * 16, srcH + W1LO + i * 16);
            }
            cp_commit();
        }
        // MMA chunk kc
        {
            const uint32_t aB = sb + AB_OFF + buf * AB_BUF + aoff;
            const uint32_t bB = sb + BBF_OFF + buf * BBF_BUF + boff1;
            #pragma unroll
            for (int kk = 0; kk < 2; kk++) {
                const uint32_t kb2 = kk * 32;
                uint32_t ah[4], al[4];
                ldm4(ah, aB + kb2);
                ldm4(al, aB + AB_SPL + kb2);
                #pragma unroll
                for (int p = 0; p < 8; p++) {
                    uint32_t bhf[4], blf[4];
                    ldm4(bhf, bB + p * 1280 + kb2);
                    ldm4(blf, bB + BBF_SPL + p * 1280 + kb2);
                    float* A0 = acc[2 * p];
                    float* A1 = acc[2 * p + 1];
                    mma_bf16(A0, ah[0], ah[1], ah[2], ah[3], bhf[0], bhf[1]);
                    mma_bf16(A0, ah[0], ah[1], ah[2], ah[3], blf[0], blf[1]);
                    mma_bf16(A0, al[0], al[1], al[2], al[3], bhf[0], bhf[1]);
                    mma_bf16(A1, ah[0], ah[1], ah[2], ah[3], bhf[2], bhf[3]);
                    mma_bf16(A1, ah[0], ah[1], ah[2], ah[3], blf[2], blf[3]);
                    mma_bf16(A1, al[0], al[1], al[2], al[3], bhf[2], bhf[3]);
                }
            }
        }
        if (kc + 1 < NC1) {
            char* Ah = dsm + AB_OFF + (buf ^ 1) * AB_BUF;
            #pragma unroll
            for (int j = 0; j < 2; j++) {
                int item = tid + j * NT;
                int r = item >> 3, f = item & 7;
                uint32_t h0, l0, h1, l1;
                split2(va[j].x, va[j].y, h0, l0);
                split2(va[j].z, va[j].w, h1, l1);
                *(uint2*)(Ah + r * 80 + f * 8) = make_uint2(h0, h1);
                *(uint2*)(Ah + AB_SPL + r * 80 + f * 8) = make_uint2(l0, l1);
            }
            if (kc + 2 < NC1) {
                #pragma unroll
                for (int j = 0; j < 2; j++) {
                    int item = tid + j * NT;
                    int r = item >> 3, f = item & 7;
                    int p = prow[r];
                    va[j] = (p >= 0)
                          ? __ldg((const float4*)(rep + (size_t)p * DD + (kc + 2) * 32 + f * 4))
                          : make_float4(0.f, 0.f, 0.f, 0.f);
                }
            }
            cp_wait0();
        }
        __syncthreads();
    }

    // ---- prefetch Wh chunk 0 (region disjoint from H1, BBUF dead after sync) ----
    {
        #pragma unroll 1
        for (int i = tid; i < 960; i += NT) {
            cp16(sb + WB_OFF + i * 16,          whg + i * 16);
            cp16(sb + WB_OFF + WB_SPL + i * 16, whg + WHLO + i * 16);
        }
        cp_commit();
    }

    // ---- H1 = D1 + b1 (NO relu — reference quirk) -> chunked swizzled smem ----
    {
        char* Hh = dsm;
        char* Hl = dsm + H1_LO_OFF;
        const int C0 = wn * 128;
        #pragma unroll
        for (int nt = 0; nt < 16; nt++) {
            int c0i = C0 + nt * 8 + 2 * t;
            int chunk = c0i >> 5, kin = c0i & 31;
            int r0 = R0 + g, r1 = R0 + 8 + g;
            uint32_t h, l;
            float v0 = acc[nt][0] + b1s[c0i];
            float v1 = acc[nt][1] + b1s[c0i + 1];
            split2(v0, v1, h, l);
            uint32_t o0 = chunk * H1_CHK + r0 * 64 + ((kin * 2) ^ ((r0 & 3) << 4));
            *(uint32_t*)(Hh + o0) = h;
            *(uint32_t*)(Hl + o0) = l;
            float v2 = acc[nt][2] + b1s[c0i];
            float v3 = acc[nt][3] + b1s[c0i + 1];
            split2(v2, v3, h, l);
            uint32_t o1 = chunk * H1_CHK + r1 * 64 + ((kin * 2) ^ ((r1 & 3) << 4));
            *(uint32_t*)(Hh + o1) = h;
            *(uint32_t*)(Hl + o1) = l;
        }
    }
    cp_wait0();
    __syncthreads();

    // ================== LAYER 2: D2[64x192] = H1 @ Wh[e]^T ==================
    float acc2[12][4];
    #pragma unroll
    for (int nt = 0; nt < 12; nt++)
        #pragma unroll
        for (int q = 0; q < 4; q++) acc2[nt][q] = 0.f;

    for (int kc = 0; kc < NC2; kc++) {
        {
            const uint32_t bB = sb + WB_OFF + boff2;
            const uint32_t aH = sb + kc * H1_CHK + h1off;
            #pragma unroll
            for (int kk = 0; kk < 2; kk++) {
                const uint32_t kb2 = kk * 32;
                const uint32_t colsw = (kb2 + ahi16) ^ h1sw;
                uint32_t ah[4], al[4];
                ldm4(ah, aH + colsw);
                ldm4(al, aH + H1_LO_OFF + colsw);
                #pragma unroll
                for (int p = 0; p < 6; p++) {
                    uint32_t bhf[4], blf[4];
                    ldm4(bhf, bB + p * 1280 + kb2);
                    ldm4(blf, bB + WB_SPL + p * 1280 + kb2);
                    float* A0 = acc2[2 * p];
                    float* A1 = acc2[2 * p + 1];
                    mma_bf16(A0, ah[0], ah[1], ah[2], ah[3], bhf[0], bhf[1]);
                    mma_bf16(A0, ah[0], ah[1], ah[2], ah[3], blf[0], blf[1]);
                    mma_bf16(A0, al[0], al[1], al[2], al[3], bhf[0], bhf[1]);
                    mma_bf16(A1, ah[0], ah[1], ah[2], ah[3], bhf[2], bhf[3]);
                    mma_bf16(A1, ah[0], ah[1], ah[2], ah[3], blf[2], blf[3]);
                    mma_bf16(A1, al[0], al[1], al[2], al[3], bhf[2], bhf[3]);
                }
            }
        }
        __syncthreads();
        if (kc + 1 < NC2) {
            const char* srcH = whg + (size_t)(kc + 1) * WHCHUNK;
            #pragma unroll 1
            for (int i = tid; i < 960; i += NT) {
                cp16(sb + WB_OFF + i * 16,          srcH + i * 16);
                cp16(sb + WB_OFF + WB_SPL + i * 16, srcH + WHLO + i * 16);
            }
            cp_commit();
            cp_wait0();
            __syncthreads();
        }
    }

    // ---- fused epilogue: E = relu(D2 + bh) . W2 + b2 ----
    {
        const int C0 = wn * 96;
        float p0 = 0.f, p1 = 0.f;
        #pragma unroll
        for (int nt = 0; nt < 12; nt++) {
            int c0i = C0 + nt * 8 + 2 * t;
            float bb0 = bhs[c0i],     w0 = w2s[c0i];
            float bb1 = bhs[c0i + 1], w1v = w2s[c0i + 1];
            float v;
            v = acc2[nt][0] + bb0; v = v > 0.f ? v : 0.f; p0 = fmaf(v, w0,  p0);
            v = acc2[nt][1] + bb1; v = v > 0.f ? v : 0.f; p0 = fmaf(v, w1v, p0);
            v = acc2[nt][2] + bb0; v = v > 0.f ? v : 0.f; p1 = fmaf(v, w0,  p1);
            v = acc2[nt][3] + bb1; v = v > 0.f ? v : 0.f; p1 = fmaf(v, w1v, p1);
        }
        p0 += __shfl_xor_sync(0xffffffffu, p0, 1);
        p0 += __shfl_xor_sync(0xffffffffu, p0, 2);
        p1 += __shfl_xor_sync(0xffffffffu, p1, 1);
        p1 += __shfl_xor_sync(0xffffffffu, p1, 2);
        if (t == 0) {
            red[R0 + g][wn]     = p0;
            red[R0 + 8 + g][wn] = p1;
        }
        __syncthreads();
        if (tid < TM) {
            int pr = prow[tid];
            if (pr >= 0)
                g_atom_energy[pr] = red[tid][0] + red[tid][1] + b2[e];
        }
    }
}

// ---------------- deterministic per-batch reduction ----------------
__global__ void reduce_kernel(float* __restrict__ out) {
    __shared__ float s[256];
    int b = blockIdx.x, t = threadIdx.x;
    float v = 0.f;
    #pragma unroll
    for (int k = 0; k < AA; k += 256) v += g_atom_energy[b * AA + t + k];
    s[t] = v;
    __syncthreads();
    #pragma unroll
    for (int st = 128; st > 0; st >>= 1) {
        if (t < st) s[t] += s[t + st];
        __syncthreads();
    }
    if (t == 0) out[b] = s[0];
}

extern "C" void kernel_launch(void* const* d_in, const int* in_sizes, int n_in,
                              void* d_out, int out_size) {
    const float* rep     = (const float*)d_in[0];
    const int*   species = (const int*)  d_in[1];
    const float* W1      = (const float*)d_in[2];
    const float* b1      = (const float*)d_in[3];
    const float* Wh      = (const float*)d_in[4];
    const float* bh      = (const float*)d_in[5];
    const float* W2      = (const float*)d_in[6];
    const float* b2      = (const float*)d_in[7];
    float* out = (float*)d_out;

    cudaFuncSetAttribute(fused_mlp,
                         cudaFuncAttributeMaxDynamicSharedMemorySize, DSMEM);

    zero_counts_kernel<<<1, 32>>>();
    bucket_kernel<<<(NATOMS + 255) / 256, 256>>>(species);
    const int PREP = EE * NC1 * 256 + EE * NC2 * 192;
    prep_weights_kernel<<<(PREP + 255) / 256, 256>>>(W1, Wh);
    fused_mlp<<<MAXTILES, NT, DSMEM>>>(rep, b1, bh, W2, b2);
    reduce_kernel<<<BB, 256>>>(out);
}

// round 5
// speedup vs baseline: 3.6294x; 1.0355x over previous
#include <cuda_runtime.h>
#include <cuda_bf16.h>
#include <cstdint>

#define BB 32
#define AA 1024
#define DD 384
#define EE 4
#define H1C 256
#define H2C 192
#define NATOMS (BB*AA)
#define TM 64
#define NT 256
#define NC1 12
#define NC2 8
#define MAXTILES 516

// ---- dynamic SMEM byte map (per CTA) ----
#define AB_OFF 0
#define AB_BUF 10240
#define AB_SPL 5120
#define BBF_OFF 20480
#define BBF_BUF 40960
#define BBF_SPL 20480
#define H1_LO_OFF 32768
#define H1_CHK 4096
#define WB_OFF 65536
#define WB_SPL 15360
#define DSMEM 102400

#define W1CHUNK 20480
#define WHCHUNK 15360
#define W1LO ((size_t)EE * NC1 * W1CHUNK)
#define WHLO ((size_t)EE * NC2 * WHCHUNK)

// ---------------- device scratch ----------------
__device__ int   g_counts[EE];
__device__ int   g_perm[EE * NATOMS];
__device__ float g_atom_energy[NATOMS];
__device__ __align__(16) unsigned short g_W1b[2 * EE * NC1 * 256 * 40];
__device__ __align__(16) unsigned short g_Whb[2 * EE * NC2 * 192 * 40];

// ---------------- helpers ----------------
__device__ __forceinline__ uint32_t s2u(const void* p) {
    uint32_t a;
    asm("{ .reg .u64 t; cvta.to.shared.u64 t, %1; cvt.u32.u64 %0, t; }" : "=r"(a) : "l"(p));
    return a;
}
__device__ __forceinline__ void cp16(uint32_t dst, const void* src) {
    asm volatile("cp.async.cg.shared.global [%0], [%1], 16;" :: "r"(dst), "l"(src));
}
__device__ __forceinline__ void cp_commit() { asm volatile("cp.async.commit_group;"); }
__device__ __forceinline__ void cp_wait0()  { asm volatile("cp.async.wait_group 0;" ::: "memory"); }

__device__ __forceinline__ void split2(float x0, float x1, uint32_t& h, uint32_t& l) {
    __nv_bfloat16 h0 = __float2bfloat16_rn(x0);
    __nv_bfloat16 h1 = __float2bfloat16_rn(x1);
    float r0 = x0 - __bfloat162float(h0);
    float r1 = x1 - __bfloat162float(h1);
    __nv_bfloat16 l0 = __float2bfloat16_rn(r0);
    __nv_bfloat16 l1 = __float2bfloat16_rn(r1);
    h = (uint32_t)__bfloat16_as_ushort(h0) | ((uint32_t)__bfloat16_as_ushort(h1) << 16);
    l = (uint32_t)__bfloat16_as_ushort(l0) | ((uint32_t)__bfloat16_as_ushort(l1) << 16);
}

__device__ __forceinline__ void mma_bf16(float* d,
        const uint32_t* a, uint32_t b0, uint32_t b1) {
    asm volatile(
        "mma.sync.aligned.m16n8k16.row.col.f32.bf16.bf16.f32 "
        "{%0,%1,%2,%3}, {%4,%5,%6,%7}, {%8,%9}, {%0,%1,%2,%3};"
        : "+f"(d[0]), "+f"(d[1]), "+f"(d[2]), "+f"(d[3])
        : "r"(a[0]), "r"(a[1]), "r"(a[2]), "r"(a[3]), "r"(b0), "r"(b1));
}

__device__ __forceinline__ void ldm4(uint32_t* r, uint32_t addr) {
    asm volatile("ldmatrix.sync.aligned.m8n8.x4.shared.b16 {%0,%1,%2,%3}, [%4];"
        : "=r"(r[0]), "=r"(r[1]), "=r"(r[2]), "=r"(r[3]) : "r"(addr));
}

// ---------------- setup kernels ----------------
__global__ void zero_counts_kernel() {
    if (threadIdx.x < EE) g_counts[threadIdx.x] = 0;
}

__global__ void bucket_kernel(const int* __restrict__ species) {
    int i = blockIdx.x * blockDim.x + threadIdx.x;
    if (i < NATOMS) {
        int e = species[i];
        int pos = atomicAdd(&g_counts[e], 1);
        g_perm[e * NATOMS + pos] = i;
    }
}

__global__ void prep_weights_kernel(const float* __restrict__ W1,
                                    const float* __restrict__ Wh) {
    const int T1 = EE * NC1 * 256;
    const int T2 = EE * NC2 * 192;
    int idx = blockIdx.x * blockDim.x + threadIdx.x;
    if (idx < T1) {
        int e = idx / (NC1 * 256);
        int r = idx % (NC1 * 256);
        int chunk = r / 256, n = r % 256;
        const float* src = W1 + ((size_t)e * DD + chunk * 32) * H1C + n;
        uint4* dh = (uint4*)(g_W1b + (size_t)idx * 40);
        uint4* dl = (uint4*)((char*)dh + W1LO);
        #pragma unroll
        for (int q = 0; q < 4; q++) {
            uint32_t ph[4], pl[4];
            #pragma unroll
            for (int j = 0; j < 4; j++) {
                float w0 = src[(size_t)(q * 8 + 2 * j) * H1C];
                float w1 = src[(size_t)(q * 8 + 2 * j + 1) * H1C];
                split2(w0, w1, ph[j], pl[j]);
            }
            dh[q] = make_uint4(ph[0], ph[1], ph[2], ph[3]);
            dl[q] = make_uint4(pl[0], pl[1], pl[2], pl[3]);
        }
        dh[4] = make_uint4(0, 0, 0, 0);
        dl[4] = make_uint4(0, 0, 0, 0);
    } else if (idx < T1 + T2) {
        int i2 = idx - T1;
        int e = i2 / (NC2 * 192);
        int r = i2 % (NC2 * 192);
        int chunk = r / 192, n = r % 192;
        const float* src = Wh + ((size_t)e * H1C + chunk * 32) * H2C + n;
        uint4* dh = (uint4*)(g_Whb + (size_t)i2 * 40);
        uint4* dl = (uint4*)((char*)dh + WHLO);
        #pragma unroll
        for (int q = 0; q < 4; q++) {
            uint32_t ph[4], pl[4];
            #pragma unroll
            for (int j = 0; j < 4; j++) {
                float w0 = src[(size_t)(q * 8 + 2 * j) * H2C];
                float w1 = src[(size_t)(q * 8 + 2 * j + 1) * H2C];
                split2(w0, w1, ph[j], pl[j]);
            }
            dh[q] = make_uint4(ph[0], ph[1], ph[2], ph[3]);
            dl[q] = make_uint4(pl[0], pl[1], pl[2], pl[3]);
        }
        dh[4] = make_uint4(0, 0, 0, 0);
        dl[4] = make_uint4(0, 0, 0, 0);
    }
}

// ---------------- fused 2-layer MLP ----------------
__global__ void __launch_bounds__(NT, 2) fused_mlp(
    const float* __restrict__ rep,
    const float* __restrict__ b1, const float* __restrict__ bh,
    const float* __restrict__ W2, const float* __restrict__ b2)
{
    extern __shared__ __align__(16) char dsm[];
    __shared__ int   prow[TM];
    __shared__ float b1s[H1C];
    __shared__ float bhs[H2C];
    __shared__ float w2s[H2C];
    __shared__ float red[TM][4];

    const int tid  = threadIdx.x;
    const int w    = tid >> 5;
    const int lane = tid & 31;
    const int g    = lane >> 2;
    const int t    = lane & 3;
    const int wm   = w >> 2;       // 0..1 -> 32-row slab
    const int wn   = w & 3;        // 0..3 -> N quarter
    const int R0   = wm * 32;
    const int llow = lane & 15;
    const int ahi16 = (lane >> 4) << 4;

    // map blockIdx -> (species, tile)
    int c0 = g_counts[0], c1 = g_counts[1], c2 = g_counts[2], c3 = g_counts[3];
    int t0 = (c0 + TM - 1) / TM, t1 = (c1 + TM - 1) / TM;
    int t2 = (c2 + TM - 1) / TM, t3 = (c3 + TM - 1) / TM;
    int bid = blockIdx.x, e, tloc, cnt;
    if      (bid < t0)                { e = 0; tloc = bid;                cnt = c0; }
    else if (bid < t0 + t1)           { e = 1; tloc = bid - t0;           cnt = c1; }
    else if (bid < t0 + t1 + t2)      { e = 2; tloc = bid - t0 - t1;      cnt = c2; }
    else if (bid < t0 + t1 + t2 + t3) { e = 3; tloc = bid - t0 - t1 - t2; cnt = c3; }
    else return;

    const int row0   = tloc * TM;
    const int mcount = min(TM, cnt - row0);
    if (tid < TM)
        prow[tid] = (tid < mcount) ? g_perm[e * NATOMS + row0 + tid] : -1;
    b1s[tid] = b1[e * H1C + tid];
    if (tid < H2C) { bhs[tid] = bh[e * H2C + tid]; w2s[tid] = W2[e * H2C + tid]; }
    __syncthreads();

    const uint32_t sb = s2u(dsm);
    const char* w1g = (const char*)g_W1b + (size_t)e * NC1 * W1CHUNK;
    const char* whg = (const char*)g_Whb + (size_t)e * NC2 * WHCHUNK;

    // fragment address offsets (2x4 warp layout)
    const uint32_t aoff0 = (uint32_t)((R0 + llow) * 80 + ahi16);
    const uint32_t aoff1 = aoff0 + 16 * 80;
    const uint32_t boff1 = (uint32_t)((wn * 64 + (lane & 7) + ((lane >> 4) << 3)) * 80
                                      + (((lane >> 3) & 1) << 4));
    const uint32_t boff2 = (uint32_t)((wn * 48 + (lane & 7) + ((lane >> 4) << 3)) * 80
                                      + (((lane >> 3) & 1) << 4));
    // H1 addressing (64B rows, 16B-block XOR swizzle by row&3)
    const uint32_t h1row = (uint32_t)(R0 + llow);
    const uint32_t h1sw  = (h1row & 3) << 4;
    const uint32_t h1off0 = h1row * 64;
    const uint32_t h1off1 = h1off0 + 16 * 64;

    // ================== LAYER 1: D1[64x256] = A @ W1[e]^T ==================
    float acc[2][8][4];
    #pragma unroll
    for (int mt = 0; mt < 2; mt++)
        #pragma unroll
        for (int nt = 0; nt < 8; nt++)
            #pragma unroll
            for (int q = 0; q < 4; q++) acc[mt][nt][q] = 0.f;

    float4 va[2];
    // preamble
    {
        #pragma unroll
        for (int j = 0; j < 2; j++) {
            int item = tid + j * NT;
            int r = item >> 3, f = item & 7;
            int p = prow[r];
            va[j] = (p >= 0) ? __ldg((const float4*)(rep + (size_t)p * DD + f * 4))
                             : make_float4(0.f, 0.f, 0.f, 0.f);
        }
        #pragma unroll 1
        for (int i = tid; i < 1280; i += NT) {
            cp16(sb + BBF_OFF + i * 16,           w1g + i * 16);
            cp16(sb + BBF_OFF + BBF_SPL + i * 16, w1g + W1LO + i * 16);
        }
        cp_commit();
        char* Ah = dsm + AB_OFF;
        #pragma unroll
        for (int j = 0; j < 2; j++) {
            int item = tid + j * NT;
            int r = item >> 3, f = item & 7;
            uint32_t h0, l0, h1, l1;
            split2(va[j].x, va[j].y, h0, l0);
            split2(va[j].z, va[j].w, h1, l1);
            *(uint2*)(Ah + r * 80 + f * 8) = make_uint2(h0, h1);
            *(uint2*)(Ah + AB_SPL + r * 80 + f * 8) = make_uint2(l0, l1);
        }
        #pragma unroll
        for (int j = 0; j < 2; j++) {
            int item = tid + j * NT;
            int r = item >> 3, f = item & 7;
            int p = prow[r];
            va[j] = (p >= 0) ? __ldg((const float4*)(rep + (size_t)p * DD + 32 + f * 4))
                             : make_float4(0.f, 0.f, 0.f, 0.f);
        }
        cp_wait0();
        __syncthreads();
    }

    for (int kc = 0; kc < NC1; kc++) {
        const int buf = kc & 1;
        if (kc + 1 < NC1) {
            const int nb = buf ^ 1;
            const char* srcH = w1g + (size_t)(kc + 1) * W1CHUNK;
            #pragma unroll 1
            for (int i = tid; i < 1280; i += NT) {
                cp16(sb + BBF_OFF + nb * BBF_BUF + i * 16,           srcH + i * 16);
                cp16(sb + BBF_OFF + nb * BBF_BUF + BBF_SPL + i * 16, srcH + W1LO + i * 16);
            }
            cp_commit();
        }
        // MMA chunk kc (pipelined B fragments, distance-4 acc chains)
        {
            const uint32_t aB = sb + AB_OFF + buf * AB_BUF;
            const uint32_t bB = sb + BBF_OFF + buf * BBF_BUF + boff1;
            #pragma unroll
            for (int kk = 0; kk < 2; kk++) {
                const uint32_t kb2 = kk * 32;
                uint32_t ah0[4], al0[4], ah1[4], al1[4];
                ldm4(ah0, aB + aoff0 + kb2);
                ldm4(ah1, aB + aoff1 + kb2);
                ldm4(al0, aB + AB_SPL + aoff0 + kb2);
                ldm4(al1, aB + AB_SPL + aoff1 + kb2);
                uint32_t bhf[2][4], blf[2][4];
                ldm4(bhf[0], bB + kb2);
                ldm4(blf[0], bB + BBF_SPL + kb2);
                #pragma unroll
                for (int pg = 0; pg < 4; pg++) {
                    const int cur = pg & 1, nxt = cur ^ 1;
                    if (pg < 3) {
                        ldm4(bhf[nxt], bB + (pg + 1) * 1280 + kb2);
                        ldm4(blf[nxt], bB + BBF_SPL + (pg + 1) * 1280 + kb2);
                    }
                    float* A00 = acc[0][2 * pg];
                    float* A10 = acc[1][2 * pg];
                    float* A01 = acc[0][2 * pg + 1];
                    float* A11 = acc[1][2 * pg + 1];
                    // hh
                    mma_bf16(A00, ah0, bhf[cur][0], bhf[cur][1]);
                    mma_bf16(A10, ah1, bhf[cur][0], bhf[cur][1]);
                    mma_bf16(A01, ah0, bhf[cur][2], bhf[cur][3]);
                    mma_bf16(A11, ah1, bhf[cur][2], bhf[cur][3]);
                    // hl
                    mma_bf16(A00, ah0, blf[cur][0], blf[cur][1]);
                    mma_bf16(A10, ah1, blf[cur][0], blf[cur][1]);
                    mma_bf16(A01, ah0, blf[cur][2], blf[cur][3]);
                    mma_bf16(A11, ah1, blf[cur][2], blf[cur][3]);
                    // lh
                    mma_bf16(A00, al0, bhf[cur][0], bhf[cur][1]);
                    mma_bf16(A10, al1, bhf[cur][0], bhf[cur][1]);
                    mma_bf16(A01, al0, bhf[cur][2], bhf[cur][3]);
                    mma_bf16(A11, al1, bhf[cur][2], bhf[cur][3]);
                }
            }
        }
        if (kc + 1 < NC1) {
            char* Ah = dsm + AB_OFF + (buf ^ 1) * AB_BUF;
            #pragma unroll
            for (int j = 0; j < 2; j++) {
                int item = tid + j * NT;
                int r = item >> 3, f = item & 7;
                uint32_t h0, l0, h1, l1;
                split2(va[j].x, va[j].y, h0, l0);
                split2(va[j].z, va[j].w, h1, l1);
                *(uint2*)(Ah + r * 80 + f * 8) = make_uint2(h0, h1);
                *(uint2*)(Ah + AB_SPL + r * 80 + f * 8) = make_uint2(l0, l1);
            }
            if (kc + 2 < NC1) {
                #pragma unroll
                for (int j = 0; j < 2; j++) {
                    int item = tid + j * NT;
                    int r = item >> 3, f = item & 7;
                    int p = prow[r];
                    va[j] = (p >= 0)
                          ? __ldg((const float4*)(rep + (size_t)p * DD + (kc + 2) * 32 + f * 4))
                          : make_float4(0.f, 0.f, 0.f, 0.f);
                }
            }
            cp_wait0();
        }
        __syncthreads();
    }

    // ---- prefetch Wh chunk 0 ----
    {
        #pragma unroll 1
        for (int i = tid; i < 960; i += NT) {
            cp16(sb + WB_OFF + i * 16,          whg + i * 16);
            cp16(sb + WB_OFF + WB_SPL + i * 16, whg + WHLO + i * 16);
        }
        cp_commit();
    }

    // ---- H1 = D1 + b1 (NO relu — reference quirk) ----
    {
        char* Hh = dsm;
        char* Hl = dsm + H1_LO_OFF;
        const int C0 = wn * 64;
        #pragma unroll
        for (int mt = 0; mt < 2; mt++) {
            #pragma unroll
            for (int nt = 0; nt < 8; nt++) {
                int c0i = C0 + nt * 8 + 2 * t;
                int chunk = c0i >> 5, kin = c0i & 31;
                int r0 = R0 + mt * 16 + g, r1 = r0 + 8;
                uint32_t h, l;
                float v0 = acc[mt][nt][0] + b1s[c0i];
                float v1 = acc[mt][nt][1] + b1s[c0i + 1];
                split2(v0, v1, h, l);
                uint32_t o0 = chunk * H1_CHK + r0 * 64 + ((kin * 2) ^ ((r0 & 3) << 4));
                *(uint32_t*)(Hh + o0) = h;
                *(uint32_t*)(Hl + o0) = l;
                float v2 = acc[mt][nt][2] + b1s[c0i];
                float v3 = acc[mt][nt][3] + b1s[c0i + 1];
                split2(v2, v3, h, l);
                uint32_t o1 = chunk * H1_CHK + r1 * 64 + ((kin * 2) ^ ((r1 & 3) << 4));
                *(uint32_t*)(Hh + o1) = h;
                *(uint32_t*)(Hl + o1) = l;
            }
        }
    }
    cp_wait0();
    __syncthreads();

    // ================== LAYER 2: D2[64x192] = H1 @ Wh[e]^T ==================
    float acc2[2][6][4];
    #pragma unroll
    for (int mt = 0; mt < 2; mt++)
        #pragma unroll
        for (int nt = 0; nt < 6; nt++)
            #pragma unroll
            for (int q = 0; q < 4; q++) acc2[mt][nt][q] = 0.f;

    for (int kc = 0; kc < NC2; kc++) {
        {
            const uint32_t bB = sb + WB_OFF + boff2;
            const uint32_t aH = sb + kc * H1_CHK;
            #pragma unroll
            for (int kk = 0; kk < 2; kk++) {
                const uint32_t kb2 = kk * 32;
                const uint32_t colsw = (kb2 + ahi16) ^ h1sw;
                uint32_t ah0[4], al0[4], ah1[4], al1[4];
                ldm4(ah0, aH + h1off0 + colsw);
                ldm4(ah1, aH + h1off1 + colsw);
                ldm4(al0, aH + H1_LO_OFF + h1off0 + colsw);
                ldm4(al1, aH + H1_LO_OFF + h1off1 + colsw);
                uint32_t bhf[2][4], blf[2][4];
                ldm4(bhf[0], bB + kb2);
                ldm4(blf[0], bB + WB_SPL + kb2);
                #pragma unroll
                for (int pg = 0; pg < 3; pg++) {
                    const int cur = pg & 1, nxt = cur ^ 1;
                    if (pg < 2) {
                        ldm4(bhf[nxt], bB + (pg + 1) * 1280 + kb2);
                        ldm4(blf[nxt], bB + WB_SPL + (pg + 1) * 1280 + kb2);
                    }
                    float* A00 = acc2[0][2 * pg];
                    float* A10 = acc2[1][2 * pg];
                    float* A01 = acc2[0][2 * pg + 1];
                    float* A11 = acc2[1][2 * pg + 1];
                    mma_bf16(A00, ah0, bhf[cur][0], bhf[cur][1]);
                    mma_bf16(A10, ah1, bhf[cur][0], bhf[cur][1]);
                    mma_bf16(A01, ah0, bhf[cur][2], bhf[cur][3]);
                    mma_bf16(A11, ah1, bhf[cur][2], bhf[cur][3]);
                    mma_bf16(A00, ah0, blf[cur][0], blf[cur][1]);
                    mma_bf16(A10, ah1, blf[cur][0], blf[cur][1]);
                    mma_bf16(A01, ah0, blf[cur][2], blf[cur][3]);
                    mma_bf16(A11, ah1, blf[cur][2], blf[cur][3]);
                    mma_bf16(A00, al0, bhf[cur][0], bhf[cur][1]);
                    mma_bf16(A10, al1, bhf[cur][0], bhf[cur][1]);
                    mma_bf16(A01, al0, bhf[cur][2], bhf[cur][3]);
                    mma_bf16(A11, al1, bhf[cur][2], bhf[cur][3]);
                }
            }
        }
        __syncthreads();
        if (kc + 1 < NC2) {
            const char* srcH = whg + (size_t)(kc + 1) * WHCHUNK;
            #pragma unroll 1
            for (int i = tid; i < 960; i += NT) {
                cp16(sb + WB_OFF + i * 16,          srcH + i * 16);
                cp16(sb + WB_OFF + WB_SPL + i * 16, srcH + WHLO + i * 16);
            }
            cp_commit();
            cp_wait0();
            __syncthreads();
        }
    }

    // ---- fused epilogue: E = relu(D2 + bh) . W2 + b2 ----
    {
        const int C0 = wn * 48;
        float pv[2][2] = {{0.f, 0.f}, {0.f, 0.f}};
        #pragma unroll
        for (int mt = 0; mt < 2; mt++) {
            #pragma unroll
            for (int nt = 0; nt < 6; nt++) {
                int c0i = C0 + nt * 8 + 2 * t;
                float bb0 = bhs[c0i],     w0 = w2s[c0i];
                float bb1 = bhs[c0i + 1], w1v = w2s[c0i + 1];
                float v;
                v = acc2[mt][nt][0] + bb0; v = v > 0.f ? v : 0.f; pv[mt][0] = fmaf(v, w0,  pv[mt][0]);
                v = acc2[mt][nt][1] + bb1; v = v > 0.f ? v : 0.f; pv[mt][0] = fmaf(v, w1v, pv[mt][0]);
                v = acc2[mt][nt][2] + bb0; v = v > 0.f ? v : 0.f; pv[mt][1] = fmaf(v, w0,  pv[mt][1]);
                v = acc2[mt][nt][3] + bb1; v = v > 0.f ? v : 0.f; pv[mt][1] = fmaf(v, w1v, pv[mt][1]);
            }
        }
        #pragma unroll
        for (int mt = 0; mt < 2; mt++) {
            #pragma unroll
            for (int h = 0; h < 2; h++) {
                pv[mt][h] += __shfl_xor_sync(0xffffffffu, pv[mt][h], 1);
                pv[mt][h] += __shfl_xor_sync(0xffffffffu, pv[mt][h], 2);
            }
        }
        if (t == 0) {
            #pragma unroll
            for (int mt = 0; mt < 2; mt++) {
                red[R0 + mt * 16 + g][wn]     = pv[mt][0];
                red[R0 + mt * 16 + 8 + g][wn] = pv[mt][1];
            }
        }
        __syncthreads();
        if (tid < TM) {
            int pr = prow[tid];
            if (pr >= 0)
                g_atom_energy[pr] = red[tid][0] + red[tid][1] + red[tid][2] + red[tid][3] + b2[e];
        }
    }
}

// ---------------- deterministic per-batch reduction ----------------
__global__ void reduce_kernel(float* __restrict__ out) {
    __shared__ float s[256];
    int b = blockIdx.x, t = threadIdx.x;
    float v = 0.f;
    #pragma unroll
    for (int k = 0; k < AA; k += 256) v += g_atom_energy[b * AA + t + k];
    s[t] = v;
    __syncthreads();
    #pragma unroll
    for (int st = 128; st > 0; st >>= 1) {
        if (t < st) s[t] += s[t + st];
        __syncthreads();
    }
    if (t == 0) out[b] = s[0];
}

extern "C" void kernel_launch(void* const* d_in, const int* in_sizes, int n_in,
                              void* d_out, int out_size) {
    const float* rep     = (const float*)d_in[0];
    const int*   species = (const int*)  d_in[1];
    const float* W1      = (const float*)d_in[2];
    const float* b1      = (const float*)d_in[3];
    const float* Wh      = (const float*)d_in[4];
    const float* bh      = (const float*)d_in[5];
    const float* W2      = (const float*)d_in[6];
    const float* b2      = (const float*)d_in[7];
    float* out = (float*)d_out;

    cudaFuncSetAttribute(fused_mlp,
                         cudaFuncAttributeMaxDynamicSharedMemorySize, DSMEM);

    zero_counts_kernel<<<1, 32>>>();
    bucket_kernel<<<(NATOMS + 255) / 256, 256>>>(species);
    const int PREP = EE * NC1 * 256 + EE * NC2 * 192;
    prep_weights_kernel<<<(PREP + 255) / 256, 256>>>(W1, Wh);
    fused_mlp<<<MAXTILES, NT, DSMEM>>>(rep, b1, bh, W2, b2);
    reduce_kernel<<<BB, 256>>>(out);
}

// round 6
// speedup vs baseline: 4.6580x; 1.2834x over previous
#include <cuda_runtime.h>
#include <cuda_fp16.h>
#include <cstdint>

#define BB 32
#define AA 1024
#define DD 384
#define EE 4
#define H1C 256
#define H2C 192
#define NATOMS (BB*AA)
#define TM 64
#define NT 256
#define NC1 12
#define NC2 8
#define MAXTILES 516

// ---- dynamic SMEM byte map (per CTA) ----
#define AB_OFF 0
#define AB_BUF 10240        // per buffer: hi 5120 (64 rows x 80B) + lo 5120
#define AB_SPL 5120
#define BBF_OFF 20480
#define BBF_BUF 20480       // per buffer: 256 rows x 80B (single fp16 copy)
#define H1_LO_OFF 32768     // H1 hi at 0..32768, lo at 32768..65536
#define H1_CHK 4096
#define WB_OFF 65536        // double buffer: 192 rows x 80B each
#define WB_BUF 15360
#define DSMEM 96256

#define W1CHUNK 20480
#define WHCHUNK 15360

// ---------------- device scratch ----------------
__device__ int   g_counts[EE];
__device__ int   g_perm[EE * NATOMS];
__device__ float g_atom_energy[NATOMS];
// single-fp16 weights: [e][chunk][n][40] ushorts (80B rows, 8-pad)
__device__ __align__(16) unsigned short g_W1h[EE * NC1 * 256 * 40];
__device__ __align__(16) unsigned short g_Whh[EE * NC2 * 192 * 40];

// ---------------- helpers ----------------
__device__ __forceinline__ uint32_t s2u(const void* p) {
    uint32_t a;
    asm("{ .reg .u64 t; cvta.to.shared.u64 t, %1; cvt.u32.u64 %0, t; }" : "=r"(a) : "l"(p));
    return a;
}
__device__ __forceinline__ void cp16(uint32_t dst, const void* src) {
    asm volatile("cp.async.cg.shared.global [%0], [%1], 16;" :: "r"(dst), "l"(src));
}
__device__ __forceinline__ void cp_commit() { asm volatile("cp.async.commit_group;"); }
__device__ __forceinline__ void cp_wait0()  { asm volatile("cp.async.wait_group 0;" ::: "memory"); }

// fp16 hi/lo split of two floats, packed
__device__ __forceinline__ void split2h(float x0, float x1, uint32_t& h, uint32_t& l) {
    __half h0 = __float2half_rn(x0);
    __half h1 = __float2half_rn(x1);
    float r0 = x0 - __half2float(h0);
    float r1 = x1 - __half2float(h1);
    __half l0 = __float2half_rn(r0);
    __half l1 = __float2half_rn(r1);
    h = (uint32_t)__half_as_ushort(h0) | ((uint32_t)__half_as_ushort(h1) << 16);
    l = (uint32_t)__half_as_ushort(l0) | ((uint32_t)__half_as_ushort(l1) << 16);
}

__device__ __forceinline__ void mma_f16(float* d,
        const uint32_t* a, uint32_t b0, uint32_t b1) {
    asm volatile(
        "mma.sync.aligned.m16n8k16.row.col.f32.f16.f16.f32 "
        "{%0,%1,%2,%3}, {%4,%5,%6,%7}, {%8,%9}, {%0,%1,%2,%3};"
        : "+f"(d[0]), "+f"(d[1]), "+f"(d[2]), "+f"(d[3])
        : "r"(a[0]), "r"(a[1]), "r"(a[2]), "r"(a[3]), "r"(b0), "r"(b1));
}

__device__ __forceinline__ void ldm4(uint32_t* r, uint32_t addr) {
    asm volatile("ldmatrix.sync.aligned.m8n8.x4.shared.b16 {%0,%1,%2,%3}, [%4];"
        : "=r"(r[0]), "=r"(r[1]), "=r"(r[2]), "=r"(r[3]) : "r"(addr));
}

// ---------------- setup kernels ----------------
__global__ void zero_counts_kernel() {
    if (threadIdx.x < EE) g_counts[threadIdx.x] = 0;
}

__global__ void bucket_kernel(const int* __restrict__ species) {
    int i = blockIdx.x * blockDim.x + threadIdx.x;
    if (i < NATOMS) {
        int e = species[i];
        int pos = atomicAdd(&g_counts[e], 1);
        g_perm[e * NATOMS + pos] = i;
    }
}

// one thread per (e, chunk, n): single fp16 copy
__global__ void prep_weights_kernel(const float* __restrict__ W1,
                                    const float* __restrict__ Wh) {
    const int T1 = EE * NC1 * 256;
    const int T2 = EE * NC2 * 192;
    int idx = blockIdx.x * blockDim.x + threadIdx.x;
    if (idx < T1) {
        int e = idx / (NC1 * 256);
        int r = idx % (NC1 * 256);
        int chunk = r / 256, n = r % 256;
        const float* src = W1 + ((size_t)e * DD + chunk * 32) * H1C + n;
        uint4* dh = (uint4*)(g_W1h + (size_t)idx * 40);
        #pragma unroll
        for (int q = 0; q < 4; q++) {
            uint32_t ph[4];
            #pragma unroll
            for (int j = 0; j < 4; j++) {
                __half w0 = __float2half_rn(src[(size_t)(q * 8 + 2 * j) * H1C]);
                __half w1 = __float2half_rn(src[(size_t)(q * 8 + 2 * j + 1) * H1C]);
                ph[j] = (uint32_t)__half_as_ushort(w0) | ((uint32_t)__half_as_ushort(w1) << 16);
            }
            dh[q] = make_uint4(ph[0], ph[1], ph[2], ph[3]);
        }
        dh[4] = make_uint4(0, 0, 0, 0);
    } else if (idx < T1 + T2) {
        int i2 = idx - T1;
        int e = i2 / (NC2 * 192);
        int r = i2 % (NC2 * 192);
        int chunk = r / 192, n = r % 192;
        const float* src = Wh + ((size_t)e * H1C + chunk * 32) * H2C + n;
        uint4* dh = (uint4*)(g_Whh + (size_t)i2 * 40);
        #pragma unroll
        for (int q = 0; q < 4; q++) {
            uint32_t ph[4];
            #pragma unroll
            for (int j = 0; j < 4; j++) {
                __half w0 = __float2half_rn(src[(size_t)(q * 8 + 2 * j) * H2C]);
                __half w1 = __float2half_rn(src[(size_t)(q * 8 + 2 * j + 1) * H2C]);
                ph[j] = (uint32_t)__half_as_ushort(w0) | ((uint32_t)__half_as_ushort(w1) << 16);
            }
            dh[q] = make_uint4(ph[0], ph[1], ph[2], ph[3]);
        }
        dh[4] = make_uint4(0, 0, 0, 0);
    }
}

// ---------------- fused 2-layer MLP (fp16, split-A 2-product) ----------------
__global__ void __launch_bounds__(NT, 2) fused_mlp(
    const float* __restrict__ rep,
    const float* __restrict__ b1, const float* __restrict__ bh,
    const float* __restrict__ W2, const float* __restrict__ b2)
{
    extern __shared__ __align__(16) char dsm[];
    __shared__ int   prow[TM];
    __shared__ float b1s[H1C];
    __shared__ float bhs[H2C];
    __shared__ float w2s[H2C];
    __shared__ float red[TM][4];

    const int tid  = threadIdx.x;
    const int w    = tid >> 5;
    const int lane = tid & 31;
    const int g    = lane >> 2;
    const int t    = lane & 3;
    const int wm   = w >> 2;       // 0..1 -> 32-row slab
    const int wn   = w & 3;        // 0..3 -> N quarter
    const int R0   = wm * 32;
    const int llow = lane & 15;
    const int ahi16 = (lane >> 4) << 4;

    // map blockIdx -> (species, tile)
    int c0 = g_counts[0], c1 = g_counts[1], c2 = g_counts[2], c3 = g_counts[3];
    int t0 = (c0 + TM - 1) / TM, t1 = (c1 + TM - 1) / TM;
    int t2 = (c2 + TM - 1) / TM, t3 = (c3 + TM - 1) / TM;
    int bid = blockIdx.x, e, tloc, cnt;
    if      (bid < t0)                { e = 0; tloc = bid;                cnt = c0; }
    else if (bid < t0 + t1)           { e = 1; tloc = bid - t0;           cnt = c1; }
    else if (bid < t0 + t1 + t2)      { e = 2; tloc = bid - t0 - t1;      cnt = c2; }
    else if (bid < t0 + t1 + t2 + t3) { e = 3; tloc = bid - t0 - t1 - t2; cnt = c3; }
    else return;

    const int row0   = tloc * TM;
    const int mcount = min(TM, cnt - row0);
    if (tid < TM)
        prow[tid] = (tid < mcount) ? g_perm[e * NATOMS + row0 + tid] : -1;
    b1s[tid] = b1[e * H1C + tid];
    if (tid < H2C) { bhs[tid] = bh[e * H2C + tid]; w2s[tid] = W2[e * H2C + tid]; }
    __syncthreads();

    const uint32_t sb = s2u(dsm);
    const char* w1g = (const char*)g_W1h + (size_t)e * NC1 * W1CHUNK;
    const char* whg = (const char*)g_Whh + (size_t)e * NC2 * WHCHUNK;

    // fragment address offsets (2x4 warp layout)
    const uint32_t aoff0 = (uint32_t)((R0 + llow) * 80 + ahi16);
    const uint32_t aoff1 = aoff0 + 16 * 80;
    const uint32_t boff1 = (uint32_t)((wn * 64 + (lane & 7) + ((lane >> 4) << 3)) * 80
                                      + (((lane >> 3) & 1) << 4));
    const uint32_t boff2 = (uint32_t)((wn * 48 + (lane & 7) + ((lane >> 4) << 3)) * 80
                                      + (((lane >> 3) & 1) << 4));
    // H1 addressing (64B rows, 16B-block XOR swizzle by row&3)
    const uint32_t h1row = (uint32_t)(R0 + llow);
    const uint32_t h1sw  = (h1row & 3) << 4;
    const uint32_t h1off0 = h1row * 64;
    const uint32_t h1off1 = h1off0 + 16 * 64;

    // ================== LAYER 1: D1[64x256] = A @ W1[e]^T ==================
    float acc[2][8][4];
    #pragma unroll
    for (int mt = 0; mt < 2; mt++)
        #pragma unroll
        for (int nt = 0; nt < 8; nt++)
            #pragma unroll
            for (int q = 0; q < 4; q++) acc[mt][nt][q] = 0.f;

    float4 va[2];
    // preamble: A(0) -> abuf0, cp.async B(0) -> bbuf0, va = A(1)
    {
        #pragma unroll
        for (int j = 0; j < 2; j++) {
            int item = tid + j * NT;
            int r = item >> 3, f = item & 7;
            int p = prow[r];
            va[j] = (p >= 0) ? __ldg((const float4*)(rep + (size_t)p * DD + f * 4))
                             : make_float4(0.f, 0.f, 0.f, 0.f);
        }
        #pragma unroll 1
        for (int i = tid; i < 1280; i += NT)
            cp16(sb + BBF_OFF + i * 16, w1g + i * 16);
        cp_commit();
        char* Ah = dsm + AB_OFF;
        #pragma unroll
        for (int j = 0; j < 2; j++) {
            int item = tid + j * NT;
            int r = item >> 3, f = item & 7;
            uint32_t h0, l0, h1, l1;
            split2h(va[j].x, va[j].y, h0, l0);
            split2h(va[j].z, va[j].w, h1, l1);
            *(uint2*)(Ah + r * 80 + f * 8) = make_uint2(h0, h1);
            *(uint2*)(Ah + AB_SPL + r * 80 + f * 8) = make_uint2(l0, l1);
        }
        #pragma unroll
        for (int j = 0; j < 2; j++) {
            int item = tid + j * NT;
            int r = item >> 3, f = item & 7;
            int p = prow[r];
            va[j] = (p >= 0) ? __ldg((const float4*)(rep + (size_t)p * DD + 32 + f * 4))
                             : make_float4(0.f, 0.f, 0.f, 0.f);
        }
        cp_wait0();
        __syncthreads();
    }

    for (int kc = 0; kc < NC1; kc++) {
        const int buf = kc & 1;
        if (kc + 1 < NC1) {
            const int nb = buf ^ 1;
            const char* srcH = w1g + (size_t)(kc + 1) * W1CHUNK;
            #pragma unroll 1
            for (int i = tid; i < 1280; i += NT)
                cp16(sb + BBF_OFF + nb * BBF_BUF + i * 16, srcH + i * 16);
            cp_commit();
        }
        // MMA chunk kc
        {
            const uint32_t aB = sb + AB_OFF + buf * AB_BUF;
            const uint32_t bB = sb + BBF_OFF + buf * BBF_BUF + boff1;
            #pragma unroll
            for (int kk = 0; kk < 2; kk++) {
                const uint32_t kb2 = kk * 32;
                uint32_t ah0[4], al0[4], ah1[4], al1[4];
                ldm4(ah0, aB + aoff0 + kb2);
                ldm4(ah1, aB + aoff1 + kb2);
                ldm4(al0, aB + AB_SPL + aoff0 + kb2);
                ldm4(al1, aB + AB_SPL + aoff1 + kb2);
                uint32_t bf[2][4];
                ldm4(bf[0], bB + kb2);
                #pragma unroll
                for (int pg = 0; pg < 4; pg++) {
                    const int cur = pg & 1, nxt = cur ^ 1;
                    if (pg < 3) ldm4(bf[nxt], bB + (pg + 1) * 1280 + kb2);
                    float* A00 = acc[0][2 * pg];
                    float* A10 = acc[1][2 * pg];
                    float* A01 = acc[0][2 * pg + 1];
                    float* A11 = acc[1][2 * pg + 1];
                    mma_f16(A00, ah0, bf[cur][0], bf[cur][1]);
                    mma_f16(A10, ah1, bf[cur][0], bf[cur][1]);
                    mma_f16(A01, ah0, bf[cur][2], bf[cur][3]);
                    mma_f16(A11, ah1, bf[cur][2], bf[cur][3]);
                    mma_f16(A00, al0, bf[cur][0], bf[cur][1]);
                    mma_f16(A10, al1, bf[cur][0], bf[cur][1]);
                    mma_f16(A01, al0, bf[cur][2], bf[cur][3]);
                    mma_f16(A11, al1, bf[cur][2], bf[cur][3]);
                }
            }
        }
        if (kc + 1 < NC1) {
            char* Ah = dsm + AB_OFF + (buf ^ 1) * AB_BUF;
            #pragma unroll
            for (int j = 0; j < 2; j++) {
                int item = tid + j * NT;
                int r = item >> 3, f = item & 7;
                uint32_t h0, l0, h1, l1;
                split2h(va[j].x, va[j].y, h0, l0);
                split2h(va[j].z, va[j].w, h1, l1);
                *(uint2*)(Ah + r * 80 + f * 8) = make_uint2(h0, h1);
                *(uint2*)(Ah + AB_SPL + r * 80 + f * 8) = make_uint2(l0, l1);
            }
            if (kc + 2 < NC1) {
                #pragma unroll
                for (int j = 0; j < 2; j++) {
                    int item = tid + j * NT;
                    int r = item >> 3, f = item & 7;
                    int p = prow[r];
                    va[j] = (p >= 0)
                          ? __ldg((const float4*)(rep + (size_t)p * DD + (kc + 2) * 32 + f * 4))
                          : make_float4(0.f, 0.f, 0.f, 0.f);
                }
            }
            cp_wait0();
        }
        __syncthreads();
    }

    // ---- prefetch Wh chunk 0 into WB buf0 ----
    {
        #pragma unroll 1
        for (int i = tid; i < 960; i += NT)
            cp16(sb + WB_OFF + i * 16, whg + i * 16);
        cp_commit();
    }

    // ---- H1 = D1 + b1 (NO relu — reference quirk) -> chunked swizzled smem ----
    {
        char* Hh = dsm;
        char* Hl = dsm + H1_LO_OFF;
        const int C0 = wn * 64;
        #pragma unroll
        for (int mt = 0; mt < 2; mt++) {
            #pragma unroll
            for (int nt = 0; nt < 8; nt++) {
                int c0i = C0 + nt * 8 + 2 * t;
                int chunk = c0i >> 5, kin = c0i & 31;
                int r0 = R0 + mt * 16 + g, r1 = r0 + 8;
                uint32_t h, l;
                float v0 = acc[mt][nt][0] + b1s[c0i];
                float v1 = acc[mt][nt][1] + b1s[c0i + 1];
                split2h(v0, v1, h, l);
                uint32_t o0 = chunk * H1_CHK + r0 * 64 + ((kin * 2) ^ ((r0 & 3) << 4));
                *(uint32_t*)(Hh + o0) = h;
                *(uint32_t*)(Hl + o0) = l;
                float v2 = acc[mt][nt][2] + b1s[c0i];
                float v3 = acc[mt][nt][3] + b1s[c0i + 1];
                split2h(v2, v3, h, l);
                uint32_t o1 = chunk * H1_CHK + r1 * 64 + ((kin * 2) ^ ((r1 & 3) << 4));
                *(uint32_t*)(Hh + o1) = h;
                *(uint32_t*)(Hl + o1) = l;
            }
        }
    }
    cp_wait0();
    __syncthreads();

    // ================== LAYER 2: D2[64x192] = H1 @ Wh[e]^T (double-buffered Wh) ==================
    float acc2[2][6][4];
    #pragma unroll
    for (int mt = 0; mt < 2; mt++)
        #pragma unroll
        for (int nt = 0; nt < 6; nt++)
            #pragma unroll
            for (int q = 0; q < 4; q++) acc2[mt][nt][q] = 0.f;

    for (int kc = 0; kc < NC2; kc++) {
        const int buf = kc & 1;
        if (kc + 1 < NC2) {
            const char* srcH = whg + (size_t)(kc + 1) * WHCHUNK;
            #pragma unroll 1
            for (int i = tid; i < 960; i += NT)
                cp16(sb + WB_OFF + (buf ^ 1) * WB_BUF + i * 16, srcH + i * 16);
            cp_commit();
        }
        {
            const uint32_t bB = sb + WB_OFF + buf * WB_BUF + boff2;
            const uint32_t aH = sb + kc * H1_CHK;
            #pragma unroll
            for (int kk = 0; kk < 2; kk++) {
                const uint32_t kb2 = kk * 32;
                const uint32_t colsw = (kb2 + ahi16) ^ h1sw;
                uint32_t ah0[4], al0[4], ah1[4], al1[4];
                ldm4(ah0, aH + h1off0 + colsw);
                ldm4(ah1, aH + h1off1 + colsw);
                ldm4(al0, aH + H1_LO_OFF + h1off0 + colsw);
                ldm4(al1, aH + H1_LO_OFF + h1off1 + colsw);
                uint32_t bf[2][4];
                ldm4(bf[0], bB + kb2);
                #pragma unroll
                for (int pg = 0; pg < 3; pg++) {
                    const int cur = pg & 1, nxt = cur ^ 1;
                    if (pg < 2) ldm4(bf[nxt], bB + (pg + 1) * 1280 + kb2);
                    float* A00 = acc2[0][2 * pg];
                    float* A10 = acc2[1][2 * pg];
                    float* A01 = acc2[0][2 * pg + 1];
                    float* A11 = acc2[1][2 * pg + 1];
                    mma_f16(A00, ah0, bf[cur][0], bf[cur][1]);
                    mma_f16(A10, ah1, bf[cur][0], bf[cur][1]);
                    mma_f16(A01, ah0, bf[cur][2], bf[cur][3]);
                    mma_f16(A11, ah1, bf[cur][2], bf[cur][3]);
                    mma_f16(A00, al0, bf[cur][0], bf[cur][1]);
                    mma_f16(A10, al1, bf[cur][0], bf[cur][1]);
                    mma_f16(A01, al0, bf[cur][2], bf[cur][3]);
                    mma_f16(A11, al1, bf[cur][2], bf[cur][3]);
                }
            }
        }
        if (kc + 1 < NC2) cp_wait0();
        __syncthreads();
    }

    // ---- fused epilogue: E = relu(D2 + bh) . W2 + b2 ----
    {
        const int C0 = wn * 48;
        float pv[2][2] = {{0.f, 0.f}, {0.f, 0.f}};
        #pragma unroll
        for (int mt = 0; mt < 2; mt++) {
            #pragma unroll
            for (int nt = 0; nt < 6; nt++) {
                int c0i = C0 + nt * 8 + 2 * t;
                float bb0 = bhs[c0i],     w0 = w2s[c0i];
                float bb1 = bhs[c0i + 1], w1v = w2s[c0i + 1];
                float v;
                v = acc2[mt][nt][0] + bb0; v = v > 0.f ? v : 0.f; pv[mt][0] = fmaf(v, w0,  pv[mt][0]);
                v = acc2[mt][nt][1] + bb1; v = v > 0.f ? v : 0.f; pv[mt][0] = fmaf(v, w1v, pv[mt][0]);
                v = acc2[mt][nt][2] + bb0; v = v > 0.f ? v : 0.f; pv[mt][1] = fmaf(v, w0,  pv[mt][1]);
                v = acc2[mt][nt][3] + bb1; v = v > 0.f ? v : 0.f; pv[mt][1] = fmaf(v, w1v, pv[mt][1]);
            }
        }
        #pragma unroll
        for (int mt = 0; mt < 2; mt++) {
            #pragma unroll
            for (int h = 0; h < 2; h++) {
                pv[mt][h] += __shfl_xor_sync(0xffffffffu, pv[mt][h], 1);
                pv[mt][h] += __shfl_xor_sync(0xffffffffu, pv[mt][h], 2);
            }
        }
        if (t == 0) {
            #pragma unroll
            for (int mt = 0; mt < 2; mt++) {
                red[R0 + mt * 16 + g][wn]     = pv[mt][0];
                red[R0 + mt * 16 + 8 + g][wn] = pv[mt][1];
            }
        }
        __syncthreads();
        if (tid < TM) {
            int pr = prow[tid];
            if (pr >= 0)
                g_atom_energy[pr] = red[tid][0] + red[tid][1] + red[tid][2] + red[tid][3] + b2[e];
        }
    }
}

// ---------------- deterministic per-batch reduction ----------------
__global__ void reduce_kernel(float* __restrict__ out) {
    __shared__ float s[256];
    int b = blockIdx.x, t = threadIdx.x;
    float v = 0.f;
    #pragma unroll
    for (int k = 0; k < AA; k += 256) v += g_atom_energy[b * AA + t + k];
    s[t] = v;
    __syncthreads();
    #pragma unroll
    for (int st = 128; st > 0; st >>= 1) {
        if (t < st) s[t] += s[t + st];
        __syncthreads();
    }
    if (t == 0) out[b] = s[0];
}

extern "C" void kernel_launch(void* const* d_in, const int* in_sizes, int n_in,
                              void* d_out, int out_size) {
    const float* rep     = (const float*)d_in[0];
    const int*   species = (const int*)  d_in[1];
    const float* W1      = (const float*)d_in[2];
    const float* b1      = (const float*)d_in[3];
    const float* Wh      = (const float*)d_in[4];
    const float* bh      = (const float*)d_in[5];
    const float* W2      = (const float*)d_in[6];
    const float* b2      = (const float*)d_in[7];
    float* out = (float*)d_out;

    cudaFuncSetAttribute(fused_mlp,
                         cudaFuncAttributeMaxDynamicSharedMemorySize, DSMEM);

    zero_counts_kernel<<<1, 32>>>();
    bucket_kernel<<<(NATOMS + 255) / 256, 256>>>(species);
    const int PREP = EE * NC1 * 256 + EE * NC2 * 192;
    prep_weights_kernel<<<(PREP + 255) / 256, 256>>>(W1, Wh);
    fused_mlp<<<MAXTILES, NT, DSMEM>>>(rep, b1, bh, W2, b2);
    reduce_kernel<<<BB, 256>>>(out);
}

// round 7
// speedup vs baseline: 4.9310x; 1.0586x over previous
#include <cuda_runtime.h>
#include <cuda_fp16.h>
#include <cstdint>

#define BB 32
#define AA 1024
#define DD 384
#define EE 4
#define H1C 256
#define H2C 192
#define NATOMS (BB*AA)
#define TM 64
#define NT 256
#define NC1 12
#define NC2 8
#define MAXTILES 516

// ---- dynamic SMEM byte map (per CTA) ----
#define AB_OFF 0
#define AB_BUF 10240
#define AB_SPL 5120
#define BBF_OFF 20480
#define BBF_BUF 20480
#define H1_LO_OFF 32768
#define H1_CHK 4096
#define WB_OFF 65536
#define WB_BUF 15360
#define DSMEM 96256

#define W1CHUNK 20480
#define WHCHUNK 15360

// ---------------- device scratch ----------------
__device__ int   g_counts[EE];
__device__ int   g_perm[EE * NATOMS];
__device__ __align__(16) unsigned short g_W1h[EE * NC1 * 256 * 40];
__device__ __align__(16) unsigned short g_Whh[EE * NC2 * 192 * 40];

// ---------------- helpers ----------------
__device__ __forceinline__ uint32_t s2u(const void* p) {
    uint32_t a;
    asm("{ .reg .u64 t; cvta.to.shared.u64 t, %1; cvt.u32.u64 %0, t; }" : "=r"(a) : "l"(p));
    return a;
}
__device__ __forceinline__ void cp16(uint32_t dst, const void* src) {
    asm volatile("cp.async.cg.shared.global [%0], [%1], 16;" :: "r"(dst), "l"(src));
}
__device__ __forceinline__ void cp_commit() { asm volatile("cp.async.commit_group;"); }
__device__ __forceinline__ void cp_wait0()  { asm volatile("cp.async.wait_group 0;" ::: "memory"); }

__device__ __forceinline__ void split2h(float x0, float x1, uint32_t& h, uint32_t& l) {
    __half h0 = __float2half_rn(x0);
    __half h1 = __float2half_rn(x1);
    float r0 = x0 - __half2float(h0);
    float r1 = x1 - __half2float(h1);
    __half l0 = __float2half_rn(r0);
    __half l1 = __float2half_rn(r1);
    h = (uint32_t)__half_as_ushort(h0) | ((uint32_t)__half_as_ushort(h1) << 16);
    l = (uint32_t)__half_as_ushort(l0) | ((uint32_t)__half_as_ushort(l1) << 16);
}

__device__ __forceinline__ void mma_f16(float* d,
        const uint32_t* a, uint32_t b0, uint32_t b1) {
    asm volatile(
        "mma.sync.aligned.m16n8k16.row.col.f32.f16.f16.f32 "
        "{%0,%1,%2,%3}, {%4,%5,%6,%7}, {%8,%9}, {%0,%1,%2,%3};"
        : "+f"(d[0]), "+f"(d[1]), "+f"(d[2]), "+f"(d[3])
        : "r"(a[0]), "r"(a[1]), "r"(a[2]), "r"(a[3]), "r"(b0), "r"(b1));
}

__device__ __forceinline__ void ldm4(uint32_t* r, uint32_t addr) {
    asm volatile("ldmatrix.sync.aligned.m8n8.x4.shared.b16 {%0,%1,%2,%3}, [%4];"
        : "=r"(r[0]), "=r"(r[1]), "=r"(r[2]), "=r"(r[3]) : "r"(addr));
}

// ---------------- setup kernels ----------------
__global__ void zero_kernel(float* __restrict__ out) {
    if (threadIdx.x < EE) g_counts[threadIdx.x] = 0;
    if (threadIdx.x < BB) out[threadIdx.x] = 0.f;
}

__global__ void bucket_kernel(const int* __restrict__ species) {
    int i = blockIdx.x * blockDim.x + threadIdx.x;
    if (i < NATOMS) {
        int e = species[i];
        int pos = atomicAdd(&g_counts[e], 1);
        g_perm[e * NATOMS + pos] = i;
    }
}

__global__ void prep_weights_kernel(const float* __restrict__ W1,
                                    const float* __restrict__ Wh) {
    const int T1 = EE * NC1 * 256;
    const int T2 = EE * NC2 * 192;
    int idx = blockIdx.x * blockDim.x + threadIdx.x;
    if (idx < T1) {
        int e = idx / (NC1 * 256);
        int r = idx % (NC1 * 256);
        int chunk = r / 256, n = r % 256;
        const float* src = W1 + ((size_t)e * DD + chunk * 32) * H1C + n;
        uint4* dh = (uint4*)(g_W1h + (size_t)idx * 40);
        #pragma unroll
        for (int q = 0; q < 4; q++) {
            uint32_t ph[4];
            #pragma unroll
            for (int j = 0; j < 4; j++) {
                __half w0 = __float2half_rn(src[(size_t)(q * 8 + 2 * j) * H1C]);
                __half w1 = __float2half_rn(src[(size_t)(q * 8 + 2 * j + 1) * H1C]);
                ph[j] = (uint32_t)__half_as_ushort(w0) | ((uint32_t)__half_as_ushort(w1) << 16);
            }
            dh[q] = make_uint4(ph[0], ph[1], ph[2], ph[3]);
        }
        dh[4] = make_uint4(0, 0, 0, 0);
    } else if (idx < T1 + T2) {
        int i2 = idx - T1;
        int e = i2 / (NC2 * 192);
        int r = i2 % (NC2 * 192);
        int chunk = r / 192, n = r % 192;
        const float* src = Wh + ((size_t)e * H1C + chunk * 32) * H2C + n;
        uint4* dh = (uint4*)(g_Whh + (size_t)i2 * 40);
        #pragma unroll
        for (int q = 0; q < 4; q++) {
            uint32_t ph[4];
            #pragma unroll
            for (int j = 0; j < 4; j++) {
                __half w0 = __float2half_rn(src[(size_t)(q * 8 + 2 * j) * H2C]);
                __half w1 = __float2half_rn(src[(size_t)(q * 8 + 2 * j + 1) * H2C]);
                ph[j] = (uint32_t)__half_as_ushort(w0) | ((uint32_t)__half_as_ushort(w1) << 16);
            }
            dh[q] = make_uint4(ph[0], ph[1], ph[2], ph[3]);
        }
        dh[4] = make_uint4(0, 0, 0, 0);
    }
}

// ---------------- fused 2-layer MLP + batch reduction ----------------
__global__ void __launch_bounds__(NT, 2) fused_mlp(
    const float* __restrict__ rep,
    const float* __restrict__ b1, const float* __restrict__ bh,
    const float* __restrict__ W2, const float* __restrict__ b2,
    float* __restrict__ outp)
{
    extern __shared__ __align__(16) char dsm[];
    __shared__ int   prow[TM];
    __shared__ float b1s[H1C];
    __shared__ float bhs[H2C];
    __shared__ float w2s[H2C];
    __shared__ float red[TM][4];
    __shared__ float bins[BB];

    const int tid  = threadIdx.x;
    const int w    = tid >> 5;
    const int lane = tid & 31;
    const int g    = lane >> 2;
    const int t    = lane & 3;
    const int wm   = w >> 2;
    const int wn   = w & 3;
    const int R0   = wm * 32;
    const int llow = lane & 15;
    const int ahi16 = (lane >> 4) << 4;

    // map blockIdx -> (species, tile)
    int c0 = g_counts[0], c1 = g_counts[1], c2 = g_counts[2], c3 = g_counts[3];
    int t0 = (c0 + TM - 1) / TM, t1 = (c1 + TM - 1) / TM;
    int t2 = (c2 + TM - 1) / TM, t3 = (c3 + TM - 1) / TM;
    int bid = blockIdx.x, e, tloc, cnt;
    if      (bid < t0)                { e = 0; tloc = bid;                cnt = c0; }
    else if (bid < t0 + t1)           { e = 1; tloc = bid - t0;           cnt = c1; }
    else if (bid < t0 + t1 + t2)      { e = 2; tloc = bid - t0 - t1;      cnt = c2; }
    else if (bid < t0 + t1 + t2 + t3) { e = 3; tloc = bid - t0 - t1 - t2; cnt = c3; }
    else return;

    const int row0   = tloc * TM;
    const int mcount = min(TM, cnt - row0);
    if (tid < TM)
        prow[tid] = (tid < mcount) ? g_perm[e * NATOMS + row0 + tid] : -1;
    b1s[tid] = b1[e * H1C + tid];
    if (tid < H2C) { bhs[tid] = bh[e * H2C + tid]; w2s[tid] = W2[e * H2C + tid]; }
    if (tid < BB) bins[tid] = 0.f;
    __syncthreads();

    const uint32_t sb = s2u(dsm);
    const char* w1g = (const char*)g_W1h + (size_t)e * NC1 * W1CHUNK;
    const char* whg = (const char*)g_Whh + (size_t)e * NC2 * WHCHUNK;

    const uint32_t aoff0 = (uint32_t)((R0 + llow) * 80 + ahi16);
    const uint32_t aoff1 = aoff0 + 16 * 80;
    const uint32_t boff1 = (uint32_t)((wn * 64 + (lane & 7) + ((lane >> 4) << 3)) * 80
                                      + (((lane >> 3) & 1) << 4));
    const uint32_t boff2 = (uint32_t)((wn * 48 + (lane & 7) + ((lane >> 4) << 3)) * 80
                                      + (((lane >> 3) & 1) << 4));
    const uint32_t h1row = (uint32_t)(R0 + llow);
    const uint32_t h1sw  = (h1row & 3) << 4;
    const uint32_t h1off0 = h1row * 64;
    const uint32_t h1off1 = h1off0 + 16 * 64;

    // ================== LAYER 1: D1[64x256] = A @ W1[e]^T ==================
    float acc[2][8][4];
    #pragma unroll
    for (int mt = 0; mt < 2; mt++)
        #pragma unroll
        for (int nt = 0; nt < 8; nt++)
            #pragma unroll
            for (int q = 0; q < 4; q++) acc[mt][nt][q] = 0.f;

    float4 va[2];
    // preamble
    {
        #pragma unroll
        for (int j = 0; j < 2; j++) {
            int item = tid + j * NT;
            int r = item >> 3, f = item & 7;
            int p = prow[r];
            va[j] = (p >= 0) ? __ldg((const float4*)(rep + (size_t)p * DD + f * 4))
                             : make_float4(0.f, 0.f, 0.f, 0.f);
        }
        #pragma unroll 1
        for (int i = tid; i < 1280; i += NT)
            cp16(sb + BBF_OFF + i * 16, w1g + i * 16);
        cp_commit();
        char* Ah = dsm + AB_OFF;
        #pragma unroll
        for (int j = 0; j < 2; j++) {
            int item = tid + j * NT;
            int r = item >> 3, f = item & 7;
            uint32_t h0, l0, h1, l1;
            split2h(va[j].x, va[j].y, h0, l0);
            split2h(va[j].z, va[j].w, h1, l1);
            *(uint2*)(Ah + r * 80 + f * 8) = make_uint2(h0, h1);
            *(uint2*)(Ah + AB_SPL + r * 80 + f * 8) = make_uint2(l0, l1);
        }
        #pragma unroll
        for (int j = 0; j < 2; j++) {
            int item = tid + j * NT;
            int r = item >> 3, f = item & 7;
            int p = prow[r];
            va[j] = (p >= 0) ? __ldg((const float4*)(rep + (size_t)p * DD + 32 + f * 4))
                             : make_float4(0.f, 0.f, 0.f, 0.f);
        }
        cp_wait0();
        __syncthreads();
    }

    for (int kc = 0; kc < NC1; kc++) {
        const int buf = kc & 1;
        if (kc + 1 < NC1) {
            const int nb = buf ^ 1;
            const char* srcH = w1g + (size_t)(kc + 1) * W1CHUNK;
            #pragma unroll 1
            for (int i = tid; i < 1280; i += NT)
                cp16(sb + BBF_OFF + nb * BBF_BUF + i * 16, srcH + i * 16);
            cp_commit();
        }
        // MMA chunk kc — all fragments loaded up front, burst of 32 MMAs
        {
            const uint32_t aB = sb + AB_OFF + buf * AB_BUF;
            const uint32_t bB = sb + BBF_OFF + buf * BBF_BUF + boff1;
            #pragma unroll
            for (int kk = 0; kk < 2; kk++) {
                const uint32_t kb2 = kk * 32;
                uint32_t ah0[4], al0[4], ah1[4], al1[4];
                uint32_t bf[4][4];
                ldm4(ah0, aB + aoff0 + kb2);
                ldm4(ah1, aB + aoff1 + kb2);
                ldm4(al0, aB + AB_SPL + aoff0 + kb2);
                ldm4(al1, aB + AB_SPL + aoff1 + kb2);
                ldm4(bf[0], bB + kb2);
                ldm4(bf[1], bB + 1280 + kb2);
                ldm4(bf[2], bB + 2560 + kb2);
                ldm4(bf[3], bB + 3840 + kb2);
                #pragma unroll
                for (int pg = 0; pg < 4; pg++) {
                    float* A00 = acc[0][2 * pg];
                    float* A10 = acc[1][2 * pg];
                    float* A01 = acc[0][2 * pg + 1];
                    float* A11 = acc[1][2 * pg + 1];
                    mma_f16(A00, ah0, bf[pg][0], bf[pg][1]);
                    mma_f16(A10, ah1, bf[pg][0], bf[pg][1]);
                    mma_f16(A01, ah0, bf[pg][2], bf[pg][3]);
                    mma_f16(A11, ah1, bf[pg][2], bf[pg][3]);
                    mma_f16(A00, al0, bf[pg][0], bf[pg][1]);
                    mma_f16(A10, al1, bf[pg][0], bf[pg][1]);
                    mma_f16(A01, al0, bf[pg][2], bf[pg][3]);
                    mma_f16(A11, al1, bf[pg][2], bf[pg][3]);
                }
            }
        }
        if (kc + 1 < NC1) {
            char* Ah = dsm + AB_OFF + (buf ^ 1) * AB_BUF;
            #pragma unroll
            for (int j = 0; j < 2; j++) {
                int item = tid + j * NT;
                int r = item >> 3, f = item & 7;
                uint32_t h0, l0, h1, l1;
                split2h(va[j].x, va[j].y, h0, l0);
                split2h(va[j].z, va[j].w, h1, l1);
                *(uint2*)(Ah + r * 80 + f * 8) = make_uint2(h0, h1);
                *(uint2*)(Ah + AB_SPL + r * 80 + f * 8) = make_uint2(l0, l1);
            }
            if (kc + 2 < NC1) {
                #pragma unroll
                for (int j = 0; j < 2; j++) {
                    int item = tid + j * NT;
                    int r = item >> 3, f = item & 7;
                    int p = prow[r];
                    va[j] = (p >= 0)
                          ? __ldg((const float4*)(rep + (size_t)p * DD + (kc + 2) * 32 + f * 4))
                          : make_float4(0.f, 0.f, 0.f, 0.f);
                }
            }
            cp_wait0();
        }
        __syncthreads();
    }

    // ---- prefetch Wh chunk 0 ----
    {
        #pragma unroll 1
        for (int i = tid; i < 960; i += NT)
            cp16(sb + WB_OFF + i * 16, whg + i * 16);
        cp_commit();
    }

    // ---- H1 = D1 + b1 (NO relu — reference quirk) ----
    {
        char* Hh = dsm;
        char* Hl = dsm + H1_LO_OFF;
        const int C0 = wn * 64;
        #pragma unroll
        for (int mt = 0; mt < 2; mt++) {
            #pragma unroll
            for (int nt = 0; nt < 8; nt++) {
                int c0i = C0 + nt * 8 + 2 * t;
                int chunk = c0i >> 5, kin = c0i & 31;
                int r0 = R0 + mt * 16 + g, r1 = r0 + 8;
                uint32_t h, l;
                float v0 = acc[mt][nt][0] + b1s[c0i];
                float v1 = acc[mt][nt][1] + b1s[c0i + 1];
                split2h(v0, v1, h, l);
                uint32_t o0 = chunk * H1_CHK + r0 * 64 + ((kin * 2) ^ ((r0 & 3) << 4));
                *(uint32_t*)(Hh + o0) = h;
                *(uint32_t*)(Hl + o0) = l;
                float v2 = acc[mt][nt][2] + b1s[c0i];
                float v3 = acc[mt][nt][3] + b1s[c0i + 1];
                split2h(v2, v3, h, l);
                uint32_t o1 = chunk * H1_CHK + r1 * 64 + ((kin * 2) ^ ((r1 & 3) << 4));
                *(uint32_t*)(Hh + o1) = h;
                *(uint32_t*)(Hl + o1) = l;
            }
        }
    }
    cp_wait0();
    __syncthreads();

    // ================== LAYER 2: D2[64x192] = H1 @ Wh[e]^T ==================
    float acc2[2][6][4];
    #pragma unroll
    for (int mt = 0; mt < 2; mt++)
        #pragma unroll
        for (int nt = 0; nt < 6; nt++)
            #pragma unroll
            for (int q = 0; q < 4; q++) acc2[mt][nt][q] = 0.f;

    for (int kc = 0; kc < NC2; kc++) {
        const int buf = kc & 1;
        if (kc + 1 < NC2) {
            const char* srcH = whg + (size_t)(kc + 1) * WHCHUNK;
            #pragma unroll 1
            for (int i = tid; i < 960; i += NT)
                cp16(sb + WB_OFF + (buf ^ 1) * WB_BUF + i * 16, srcH + i * 16);
            cp_commit();
        }
        {
            const uint32_t bB = sb + WB_OFF + buf * WB_BUF + boff2;
            const uint32_t aH = sb + kc * H1_CHK;
            #pragma unroll
            for (int kk = 0; kk < 2; kk++) {
                const uint32_t kb2 = kk * 32;
                const uint32_t colsw = (kb2 + ahi16) ^ h1sw;
                uint32_t ah0[4], al0[4], ah1[4], al1[4];
                uint32_t bf[3][4];
                ldm4(ah0, aH + h1off0 + colsw);
                ldm4(ah1, aH + h1off1 + colsw);
                ldm4(al0, aH + H1_LO_OFF + h1off0 + colsw);
                ldm4(al1, aH + H1_LO_OFF + h1off1 + colsw);
                ldm4(bf[0], bB + kb2);
                ldm4(bf[1], bB + 1280 + kb2);
                ldm4(bf[2], bB + 2560 + kb2);
                #pragma unroll
                for (int pg = 0; pg < 3; pg++) {
                    float* A00 = acc2[0][2 * pg];
                    float* A10 = acc2[1][2 * pg];
                    float* A01 = acc2[0][2 * pg + 1];
                    float* A11 = acc2[1][2 * pg + 1];
                    mma_f16(A00, ah0, bf[pg][0], bf[pg][1]);
                    mma_f16(A10, ah1, bf[pg][0], bf[pg][1]);
                    mma_f16(A01, ah0, bf[pg][2], bf[pg][3]);
                    mma_f16(A11, ah1, bf[pg][2], bf[pg][3]);
                    mma_f16(A00, al0, bf[pg][0], bf[pg][1]);
                    mma_f16(A10, al1, bf[pg][0], bf[pg][1]);
                    mma_f16(A01, al0, bf[pg][2], bf[pg][3]);
                    mma_f16(A11, al1, bf[pg][2], bf[pg][3]);
                }
            }
        }
        if (kc + 1 < NC2) cp_wait0();
        __syncthreads();
    }

    // ---- fused epilogue: E = relu(D2 + bh) . W2 + b2, then per-batch bins ----
    {
        const int C0 = wn * 48;
        float pv[2][2] = {{0.f, 0.f}, {0.f, 0.f}};
        #pragma unroll
        for (int mt = 0; mt < 2; mt++) {
            #pragma unroll
            for (int nt = 0; nt < 6; nt++) {
                int c0i = C0 + nt * 8 + 2 * t;
                float bb0 = bhs[c0i],     w0 = w2s[c0i];
                float bb1 = bhs[c0i + 1], w1v = w2s[c0i + 1];
                float v;
                v = acc2[mt][nt][0] + bb0; v = v > 0.f ? v : 0.f; pv[mt][0] = fmaf(v, w0,  pv[mt][0]);
                v = acc2[mt][nt][1] + bb1; v = v > 0.f ? v : 0.f; pv[mt][0] = fmaf(v, w1v, pv[mt][0]);
                v = acc2[mt][nt][2] + bb0; v = v > 0.f ? v : 0.f; pv[mt][1] = fmaf(v, w0,  pv[mt][1]);
                v = acc2[mt][nt][3] + bb1; v = v > 0.f ? v : 0.f; pv[mt][1] = fmaf(v, w1v, pv[mt][1]);
            }
        }
        #pragma unroll
        for (int mt = 0; mt < 2; mt++) {
            #pragma unroll
            for (int h = 0; h < 2; h++) {
                pv[mt][h] += __shfl_xor_sync(0xffffffffu, pv[mt][h], 1);
                pv[mt][h] += __shfl_xor_sync(0xffffffffu, pv[mt][h], 2);
            }
        }
        if (t == 0) {
            #pragma unroll
            for (int mt = 0; mt < 2; mt++) {
                red[R0 + mt * 16 + g][wn]     = pv[mt][0];
                red[R0 + mt * 16 + 8 + g][wn] = pv[mt][1];
            }
        }
        __syncthreads();
        if (tid < TM) {
            int pr = prow[tid];
            if (pr >= 0) {
                float en = red[tid][0] + red[tid][1] + red[tid][2] + red[tid][3] + b2[e];
                atomicAdd(&bins[pr >> 10], en);
            }
        }
        __syncthreads();
        if (tid < BB) {
            float v = bins[tid];
            if (v != 0.f) atomicAdd(&outp[tid], v);
        }
    }
}

extern "C" void kernel_launch(void* const* d_in, const int* in_sizes, int n_in,
                              void* d_out, int out_size) {
    const float* rep     = (const float*)d_in[0];
    const int*   species = (const int*)  d_in[1];
    const float* W1      = (const float*)d_in[2];
    const float* b1      = (const float*)d_in[3];
    const float* Wh      = (const float*)d_in[4];
    const float* bh      = (const float*)d_in[5];
    const float* W2      = (const float*)d_in[6];
    const float* b2      = (const float*)d_in[7];
    float* out = (float*)d_out;

    cudaFuncSetAttribute(fused_mlp,
                         cudaFuncAttributeMaxDynamicSharedMemorySize, DSMEM);

    zero_kernel<<<1, 32>>>(out);
    bucket_kernel<<<(NATOMS + 255) / 256, 256>>>(species);
    const int PREP = EE * NC1 * 256 + EE * NC2 * 192;
    prep_weights_kernel<<<(PREP + 255) / 256, 256>>>(W1, Wh);
    fused_mlp<<<MAXTILES, NT, DSMEM>>>(rep, b1, bh, W2, b2, out);
}

// round 8
// speedup vs baseline: 6.5559x; 1.3295x over previous
#include <cuda_runtime.h>
#include <cuda_fp16.h>
#include <cstdint>

#define BB 32
#define AA 1024
#define DD 384
#define EE 4
#define H1C 256
#define H2C 192
#define NATOMS (BB*AA)
#define TM 64
#define NT 256
#define NC1 12
#define NC2 8
#define MAXTILES 516

// ---- dynamic SMEM byte map (per CTA) ----
#define AB_OFF 0
#define AB_BUF 5120         // 64 rows x 80B, single fp16
#define BBF_OFF 10240
#define BBF_BUF 20480       // 256 rows x 80B
#define H1_OFF 0            // aliases AB/BBF after layer 1 (8 chunks x 4096)
#define H1_CHK 4096
#define WB_OFF 32768        // double buffer: 192 rows x 80B each
#define WB_BUF 15360
#define DSMEM 63488

#define W1CHUNK 20480
#define WHCHUNK 15360

// ---------------- device scratch ----------------
__device__ int   g_counts[EE];
__device__ int   g_perm[EE * NATOMS];
__device__ __align__(16) unsigned short g_W1h[EE * NC1 * 256 * 40];
__device__ __align__(16) unsigned short g_Whh[EE * NC2 * 192 * 40];

// ---------------- helpers ----------------
__device__ __forceinline__ uint32_t s2u(const void* p) {
    uint32_t a;
    asm("{ .reg .u64 t; cvta.to.shared.u64 t, %1; cvt.u32.u64 %0, t; }" : "=r"(a) : "l"(p));
    return a;
}
__device__ __forceinline__ void cp16(uint32_t dst, const void* src) {
    asm volatile("cp.async.cg.shared.global [%0], [%1], 16;" :: "r"(dst), "l"(src));
}
__device__ __forceinline__ void cp_commit() { asm volatile("cp.async.commit_group;"); }
__device__ __forceinline__ void cp_wait0()  { asm volatile("cp.async.wait_group 0;" ::: "memory"); }

__device__ __forceinline__ uint32_t pack2h(float x0, float x1) {
    __half h0 = __float2half_rn(x0);
    __half h1 = __float2half_rn(x1);
    return (uint32_t)__half_as_ushort(h0) | ((uint32_t)__half_as_ushort(h1) << 16);
}

__device__ __forceinline__ void mma_f16(float* d,
        const uint32_t* a, uint32_t b0, uint32_t b1) {
    asm volatile(
        "mma.sync.aligned.m16n8k16.row.col.f32.f16.f16.f32 "
        "{%0,%1,%2,%3}, {%4,%5,%6,%7}, {%8,%9}, {%0,%1,%2,%3};"
        : "+f"(d[0]), "+f"(d[1]), "+f"(d[2]), "+f"(d[3])
        : "r"(a[0]), "r"(a[1]), "r"(a[2]), "r"(a[3]), "r"(b0), "r"(b1));
}

__device__ __forceinline__ void ldm4(uint32_t* r, uint32_t addr) {
    asm volatile("ldmatrix.sync.aligned.m8n8.x4.shared.b16 {%0,%1,%2,%3}, [%4];"
        : "=r"(r[0]), "=r"(r[1]), "=r"(r[2]), "=r"(r[3]) : "r"(addr));
}

// ---------------- setup kernels ----------------
__global__ void zero_kernel(float* __restrict__ out) {
    if (threadIdx.x < EE) g_counts[threadIdx.x] = 0;
    if (threadIdx.x < BB) out[threadIdx.x] = 0.f;
}

__global__ void bucket_kernel(const int* __restrict__ species) {
    int i = blockIdx.x * blockDim.x + threadIdx.x;
    if (i < NATOMS) {
        int e = species[i];
        int pos = atomicAdd(&g_counts[e], 1);
        g_perm[e * NATOMS + pos] = i;
    }
}

__global__ void prep_weights_kernel(const float* __restrict__ W1,
                                    const float* __restrict__ Wh) {
    const int T1 = EE * NC1 * 256;
    const int T2 = EE * NC2 * 192;
    int idx = blockIdx.x * blockDim.x + threadIdx.x;
    if (idx < T1) {
        int e = idx / (NC1 * 256);
        int r = idx % (NC1 * 256);
        int chunk = r / 256, n = r % 256;
        const float* src = W1 + ((size_t)e * DD + chunk * 32) * H1C + n;
        uint4* dh = (uint4*)(g_W1h + (size_t)idx * 40);
        #pragma unroll
        for (int q = 0; q < 4; q++) {
            uint32_t ph[4];
            #pragma unroll
            for (int j = 0; j < 4; j++)
                ph[j] = pack2h(src[(size_t)(q * 8 + 2 * j) * H1C],
                               src[(size_t)(q * 8 + 2 * j + 1) * H1C]);
            dh[q] = make_uint4(ph[0], ph[1], ph[2], ph[3]);
        }
        dh[4] = make_uint4(0, 0, 0, 0);
    } else if (idx < T1 + T2) {
        int i2 = idx - T1;
        int e = i2 / (NC2 * 192);
        int r = i2 % (NC2 * 192);
        int chunk = r / 192, n = r % 192;
        const float* src = Wh + ((size_t)e * H1C + chunk * 32) * H2C + n;
        uint4* dh = (uint4*)(g_Whh + (size_t)i2 * 40);
        #pragma unroll
        for (int q = 0; q < 4; q++) {
            uint32_t ph[4];
            #pragma unroll
            for (int j = 0; j < 4; j++)
                ph[j] = pack2h(src[(size_t)(q * 8 + 2 * j) * H2C],
                               src[(size_t)(q * 8 + 2 * j + 1) * H2C]);
            dh[q] = make_uint4(ph[0], ph[1], ph[2], ph[3]);
        }
        dh[4] = make_uint4(0, 0, 0, 0);
    }
}

// ---------------- fused 2-layer MLP + batch reduction (fp16 1-product) ----------------
__global__ void __launch_bounds__(NT, 2) fused_mlp(
    const float* __restrict__ rep,
    const float* __restrict__ b1, const float* __restrict__ bh,
    const float* __restrict__ W2, const float* __restrict__ b2,
    float* __restrict__ outp)
{
    extern __shared__ __align__(16) char dsm[];
    __shared__ int   prow[TM];
    __shared__ float b1s[H1C];
    __shared__ float bhs[H2C];
    __shared__ float w2s[H2C];
    __shared__ float red[TM][4];
    __shared__ float bins[BB];

    const int tid  = threadIdx.x;
    const int w    = tid >> 5;
    const int lane = tid & 31;
    const int g    = lane >> 2;
    const int t    = lane & 3;
    const int wm   = w >> 2;
    const int wn   = w & 3;
    const int R0   = wm * 32;
    const int llow = lane & 15;
    const int ahi16 = (lane >> 4) << 4;

    int c0 = g_counts[0], c1 = g_counts[1], c2 = g_counts[2], c3 = g_counts[3];
    int t0 = (c0 + TM - 1) / TM, t1 = (c1 + TM - 1) / TM;
    int t2 = (c2 + TM - 1) / TM, t3 = (c3 + TM - 1) / TM;
    int bid = blockIdx.x, e, tloc, cnt;
    if      (bid < t0)                { e = 0; tloc = bid;                cnt = c0; }
    else if (bid < t0 + t1)           { e = 1; tloc = bid - t0;           cnt = c1; }
    else if (bid < t0 + t1 + t2)      { e = 2; tloc = bid - t0 - t1;      cnt = c2; }
    else if (bid < t0 + t1 + t2 + t3) { e = 3; tloc = bid - t0 - t1 - t2; cnt = c3; }
    else return;

    const int row0   = tloc * TM;
    const int mcount = min(TM, cnt - row0);
    if (tid < TM)
        prow[tid] = (tid < mcount) ? g_perm[e * NATOMS + row0 + tid] : -1;
    b1s[tid] = b1[e * H1C + tid];
    if (tid < H2C) { bhs[tid] = bh[e * H2C + tid]; w2s[tid] = W2[e * H2C + tid]; }
    if (tid < BB) bins[tid] = 0.f;
    __syncthreads();

    const uint32_t sb = s2u(dsm);
    const char* w1g = (const char*)g_W1h + (size_t)e * NC1 * W1CHUNK;
    const char* whg = (const char*)g_Whh + (size_t)e * NC2 * WHCHUNK;

    const uint32_t aoff0 = (uint32_t)((R0 + llow) * 80 + ahi16);
    const uint32_t aoff1 = aoff0 + 16 * 80;
    const uint32_t boff1 = (uint32_t)((wn * 64 + (lane & 7) + ((lane >> 4) << 3)) * 80
                                      + (((lane >> 3) & 1) << 4));
    const uint32_t boff2 = (uint32_t)((wn * 48 + (lane & 7) + ((lane >> 4) << 3)) * 80
                                      + (((lane >> 3) & 1) << 4));
    const uint32_t h1row = (uint32_t)(R0 + llow);
    const uint32_t h1sw  = (h1row & 3) << 4;
    const uint32_t h1off0 = h1row * 64;
    const uint32_t h1off1 = h1off0 + 16 * 64;

    // ================== LAYER 1: D1[64x256] = A @ W1[e]^T ==================
    float acc[2][8][4];
    #pragma unroll
    for (int mt = 0; mt < 2; mt++)
        #pragma unroll
        for (int nt = 0; nt < 8; nt++)
            #pragma unroll
            for (int q = 0; q < 4; q++) acc[mt][nt][q] = 0.f;

    float4 va[2];
    // preamble
    {
        #pragma unroll
        for (int j = 0; j < 2; j++) {
            int item = tid + j * NT;
            int r = item >> 3, f = item & 7;
            int p = prow[r];
            va[j] = (p >= 0) ? __ldg((const float4*)(rep + (size_t)p * DD + f * 4))
                             : make_float4(0.f, 0.f, 0.f, 0.f);
        }
        #pragma unroll 1
        for (int i = tid; i < 1280; i += NT)
            cp16(sb + BBF_OFF + i * 16, w1g + i * 16);
        cp_commit();
        char* Ah = dsm + AB_OFF;
        #pragma unroll
        for (int j = 0; j < 2; j++) {
            int item = tid + j * NT;
            int r = item >> 3, f = item & 7;
            *(uint2*)(Ah + r * 80 + f * 8) =
                make_uint2(pack2h(va[j].x, va[j].y), pack2h(va[j].z, va[j].w));
        }
        #pragma unroll
        for (int j = 0; j < 2; j++) {
            int item = tid + j * NT;
            int r = item >> 3, f = item & 7;
            int p = prow[r];
            va[j] = (p >= 0) ? __ldg((const float4*)(rep + (size_t)p * DD + 32 + f * 4))
                             : make_float4(0.f, 0.f, 0.f, 0.f);
        }
        cp_wait0();
        __syncthreads();
    }

    for (int kc = 0; kc < NC1; kc++) {
        const int buf = kc & 1;
        if (kc + 1 < NC1) {
            const int nb = buf ^ 1;
            const char* srcH = w1g + (size_t)(kc + 1) * W1CHUNK;
            #pragma unroll 1
            for (int i = tid; i < 1280; i += NT)
                cp16(sb + BBF_OFF + nb * BBF_BUF + i * 16, srcH + i * 16);
            cp_commit();
        }
        // MMA chunk kc
        {
            const uint32_t aB = sb + AB_OFF + buf * AB_BUF;
            const uint32_t bB = sb + BBF_OFF + buf * BBF_BUF + boff1;
            #pragma unroll
            for (int kk = 0; kk < 2; kk++) {
                const uint32_t kb2 = kk * 32;
                uint32_t ah0[4], ah1[4];
                uint32_t bf[4][4];
                ldm4(ah0, aB + aoff0 + kb2);
                ldm4(ah1, aB + aoff1 + kb2);
                ldm4(bf[0], bB + kb2);
                ldm4(bf[1], bB + 1280 + kb2);
                ldm4(bf[2], bB + 2560 + kb2);
                ldm4(bf[3], bB + 3840 + kb2);
                #pragma unroll
                for (int pg = 0; pg < 4; pg++) {
                    mma_f16(acc[0][2 * pg],     ah0, bf[pg][0], bf[pg][1]);
                    mma_f16(acc[1][2 * pg],     ah1, bf[pg][0], bf[pg][1]);
                    mma_f16(acc[0][2 * pg + 1], ah0, bf[pg][2], bf[pg][3]);
                    mma_f16(acc[1][2 * pg + 1], ah1, bf[pg][2], bf[pg][3]);
                }
            }
        }
        if (kc + 1 < NC1) {
            char* Ah = dsm + AB_OFF + (buf ^ 1) * AB_BUF;
            #pragma unroll
            for (int j = 0; j < 2; j++) {
                int item = tid + j * NT;
                int r = item >> 3, f = item & 7;
                *(uint2*)(Ah + r * 80 + f * 8) =
                    make_uint2(pack2h(va[j].x, va[j].y), pack2h(va[j].z, va[j].w));
            }
            if (kc + 2 < NC1) {
                #pragma unroll
                for (int j = 0; j < 2; j++) {
                    int item = tid + j * NT;
                    int r = item >> 3, f = item & 7;
                    int p = prow[r];
                    va[j] = (p >= 0)
                          ? __ldg((const float4*)(rep + (size_t)p * DD + (kc + 2) * 32 + f * 4))
                          : make_float4(0.f, 0.f, 0.f, 0.f);
                }
            }
            cp_wait0();
        }
        __syncthreads();
    }

    // ---- prefetch Wh chunk 0 (WB region disjoint from H1) ----
    {
        #pragma unroll 1
        for (int i = tid; i < 960; i += NT)
            cp16(sb + WB_OFF + i * 16, whg + i * 16);
        cp_commit();
    }

    // ---- H1 = D1 + b1 (NO relu — reference quirk), single fp16 ----
    {
        char* Hh = dsm + H1_OFF;
        const int C0 = wn * 64;
        #pragma unroll
        for (int mt = 0; mt < 2; mt++) {
            #pragma unroll
            for (int nt = 0; nt < 8; nt++) {
                int c0i = C0 + nt * 8 + 2 * t;
                int chunk = c0i >> 5, kin = c0i & 31;
                int r0 = R0 + mt * 16 + g, r1 = r0 + 8;
                uint32_t o0 = chunk * H1_CHK + r0 * 64 + ((kin * 2) ^ ((r0 & 3) << 4));
                *(uint32_t*)(Hh + o0) =
                    pack2h(acc[mt][nt][0] + b1s[c0i], acc[mt][nt][1] + b1s[c0i + 1]);
                uint32_t o1 = chunk * H1_CHK + r1 * 64 + ((kin * 2) ^ ((r1 & 3) << 4));
                *(uint32_t*)(Hh + o1) =
                    pack2h(acc[mt][nt][2] + b1s[c0i], acc[mt][nt][3] + b1s[c0i + 1]);
            }
        }
    }
    cp_wait0();
    __syncthreads();

    // ================== LAYER 2: D2[64x192] = H1 @ Wh[e]^T ==================
    float acc2[2][6][4];
    #pragma unroll
    for (int mt = 0; mt < 2; mt++)
        #pragma unroll
        for (int nt = 0; nt < 6; nt++)
            #pragma unroll
            for (int q = 0; q < 4; q++) acc2[mt][nt][q] = 0.f;

    for (int kc = 0; kc < NC2; kc++) {
        const int buf = kc & 1;
        if (kc + 1 < NC2) {
            const char* srcH = whg + (size_t)(kc + 1) * WHCHUNK;
            #pragma unroll 1
            for (int i = tid; i < 960; i += NT)
                cp16(sb + WB_OFF + (buf ^ 1) * WB_BUF + i * 16, srcH + i * 16);
            cp_commit();
        }
        {
            const uint32_t bB = sb + WB_OFF + buf * WB_BUF + boff2;
            const uint32_t aH = sb + H1_OFF + kc * H1_CHK;
            #pragma unroll
            for (int kk = 0; kk < 2; kk++) {
                const uint32_t kb2 = kk * 32;
                const uint32_t colsw = (kb2 + ahi16) ^ h1sw;
                uint32_t ah0[4], ah1[4];
                uint32_t bf[3][4];
                ldm4(ah0, aH + h1off0 + colsw);
                ldm4(ah1, aH + h1off1 + colsw);
                ldm4(bf[0], bB + kb2);
                ldm4(bf[1], bB + 1280 + kb2);
                ldm4(bf[2], bB + 2560 + kb2);
                #pragma unroll
                for (int pg = 0; pg < 3; pg++) {
                    mma_f16(acc2[0][2 * pg],     ah0, bf[pg][0], bf[pg][1]);
                    mma_f16(acc2[1][2 * pg],     ah1, bf[pg][0], bf[pg][1]);
                    mma_f16(acc2[0][2 * pg + 1], ah0, bf[pg][2], bf[pg][3]);
                    mma_f16(acc2[1][2 * pg + 1], ah1, bf[pg][2], bf[pg][3]);
                }
            }
        }
        if (kc + 1 < NC2) cp_wait0();
        __syncthreads();
    }

    // ---- fused epilogue: E = relu(D2 + bh) . W2 + b2, per-batch bins ----
    {
        const int C0 = wn * 48;
        float pv[2][2] = {{0.f, 0.f}, {0.f, 0.f}};
        #pragma unroll
        for (int mt = 0; mt < 2; mt++) {
            #pragma unroll
            for (int nt = 0; nt < 6; nt++) {
                int c0i = C0 + nt * 8 + 2 * t;
                float bb0 = bhs[c0i],     w0 = w2s[c0i];
                float bb1 = bhs[c0i + 1], w1v = w2s[c0i + 1];
                float v;
                v = acc2[mt][nt][0] + bb0; v = v > 0.f ? v : 0.f; pv[mt][0] = fmaf(v, w0,  pv[mt][0]);
                v = acc2[mt][nt][1] + bb1; v = v > 0.f ? v : 0.f; pv[mt][0] = fmaf(v, w1v, pv[mt][0]);
                v = acc2[mt][nt][2] + bb0; v = v > 0.f ? v : 0.f; pv[mt][1] = fmaf(v, w0,  pv[mt][1]);
                v = acc2[mt][nt][3] + bb1; v = v > 0.f ? v : 0.f; pv[mt][1] = fmaf(v, w1v, pv[mt][1]);
            }
        }
        #pragma unroll
        for (int mt = 0; mt < 2; mt++) {
            #pragma unroll
            for (int h = 0; h < 2; h++) {
                pv[mt][h] += __shfl_xor_sync(0xffffffffu, pv[mt][h], 1);
                pv[mt][h] += __shfl_xor_sync(0xffffffffu, pv[mt][h], 2);
            }
        }
        if (t == 0) {
            #pragma unroll
            for (int mt = 0; mt < 2; mt++) {
                red[R0 + mt * 16 + g][wn]     = pv[mt][0];
                red[R0 + mt * 16 + 8 + g][wn] = pv[mt][1];
            }
        }
        __syncthreads();
        if (tid < TM) {
            int pr = prow[tid];
            if (pr >= 0) {
                float en = red[tid][0] + red[tid][1] + red[tid][2] + red[tid][3] + b2[e];
                atomicAdd(&bins[pr >> 10], en);
            }
        }
        __syncthreads();
        if (tid < BB) {
            float v = bins[tid];
            if (v != 0.f) atomicAdd(&outp[tid], v);
        }
    }
}

extern "C" void kernel_launch(void* const* d_in, const int* in_sizes, int n_in,
                              void* d_out, int out_size) {
    const float* rep     = (const float*)d_in[0];
    const int*   species = (const int*)  d_in[1];
    const float* W1      = (const float*)d_in[2];
    const float* b1      = (const float*)d_in[3];
    const float* Wh      = (const float*)d_in[4];
    const float* bh      = (const float*)d_in[5];
    const float* W2      = (const float*)d_in[6];
    const float* b2      = (const float*)d_in[7];
    float* out = (float*)d_out;

    cudaFuncSetAttribute(fused_mlp,
                         cudaFuncAttributeMaxDynamicSharedMemorySize, DSMEM);

    zero_kernel<<<1, 32>>>(out);
    bucket_kernel<<<(NATOMS + 255) / 256, 256>>>(species);
    const int PREP = EE * NC1 * 256 + EE * NC2 * 192;
    prep_weights_kernel<<<(PREP + 255) / 256, 256>>>(W1, Wh);
    fused_mlp<<<MAXTILES, NT, DSMEM>>>(rep, b1, bh, W2, b2, out);
}

// round 9
// speedup vs baseline: 6.9756x; 1.0640x over previous
#include <cuda_runtime.h>
#include <cuda_fp16.h>
#include <cstdint>

#define BB 32
#define AA 1024
#define DD 384
#define EE 4
#define H1C 256
#define H2C 192
#define NATOMS (BB*AA)
#define TM 128
#define NT 512
#define NC1 12
#define NC2 8
#define MAXTILES 260

// ---- dynamic SMEM byte map (per CTA) ----
#define AB_OFF 0
#define AB_BUF 10240        // 128 rows x 80B fp16, double buffered
#define BBF_OFF 20480
#define BBF_BUF 20480       // 256 rows x 80B, double buffered
#define H1_OFF 0            // aliases AB/BBF after layer 1: 8 chunks x 8192
#define H1_CHK 8192
#define WB_OFF 65536        // 192 rows x 80B, double buffered
#define WB_BUF 15360
#define DSMEM 96256

#define W1CHUNK 20480
#define WHCHUNK 15360

// ---------------- device scratch ----------------
__device__ int   g_counts[EE];
__device__ int   g_perm[EE * NATOMS];
__device__ __align__(16) unsigned short g_W1h[EE * NC1 * 256 * 40];
__device__ __align__(16) unsigned short g_Whh[EE * NC2 * 192 * 40];

// ---------------- helpers ----------------
__device__ __forceinline__ uint32_t s2u(const void* p) {
    uint32_t a;
    asm("{ .reg .u64 t; cvta.to.shared.u64 t, %1; cvt.u32.u64 %0, t; }" : "=r"(a) : "l"(p));
    return a;
}
__device__ __forceinline__ void cp16(uint32_t dst, const void* src) {
    asm volatile("cp.async.cg.shared.global [%0], [%1], 16;" :: "r"(dst), "l"(src));
}
__device__ __forceinline__ void cp_commit() { asm volatile("cp.async.commit_group;"); }
__device__ __forceinline__ void cp_wait0()  { asm volatile("cp.async.wait_group 0;" ::: "memory"); }

__device__ __forceinline__ uint32_t pack2h(float x0, float x1) {
    __half h0 = __float2half_rn(x0);
    __half h1 = __float2half_rn(x1);
    return (uint32_t)__half_as_ushort(h0) | ((uint32_t)__half_as_ushort(h1) << 16);
}

__device__ __forceinline__ void mma_f16(float* d,
        const uint32_t* a, uint32_t b0, uint32_t b1) {
    asm volatile(
        "mma.sync.aligned.m16n8k16.row.col.f32.f16.f16.f32 "
        "{%0,%1,%2,%3}, {%4,%5,%6,%7}, {%8,%9}, {%0,%1,%2,%3};"
        : "+f"(d[0]), "+f"(d[1]), "+f"(d[2]), "+f"(d[3])
        : "r"(a[0]), "r"(a[1]), "r"(a[2]), "r"(a[3]), "r"(b0), "r"(b1));
}

__device__ __forceinline__ void ldm4(uint32_t* r, uint32_t addr) {
    asm volatile("ldmatrix.sync.aligned.m8n8.x4.shared.b16 {%0,%1,%2,%3}, [%4];"
        : "=r"(r[0]), "=r"(r[1]), "=r"(r[2]), "=r"(r[3]) : "r"(addr));
}

// ---------------- setup kernels ----------------
__global__ void zero_kernel(float* __restrict__ out) {
    if (threadIdx.x < EE) g_counts[threadIdx.x] = 0;
    if (threadIdx.x < BB) out[threadIdx.x] = 0.f;
}

// blocks [0,128): bucket atoms (warp-aggregated atomics)
// blocks [128,200): prep fp16 weights
__global__ void bucket_prep_kernel(const int* __restrict__ species,
                                   const float* __restrict__ W1,
                                   const float* __restrict__ Wh) {
    const int tid = threadIdx.x;
    const int b = blockIdx.x;
    if (b < 128) {
        int i = b * 256 + tid;
        int lane = tid & 31;
        int e = species[i];
        unsigned mask = __match_any_sync(0xffffffffu, e);
        int leader = __ffs(mask) - 1;
        int rank = __popc(mask & ((1u << lane) - 1u));
        int base = 0;
        if (lane == leader) base = atomicAdd(&g_counts[e], __popc(mask));
        base = __shfl_sync(0xffffffffu, base, leader);
        g_perm[e * NATOMS + base + rank] = i;
        return;
    }
    const int T1 = EE * NC1 * 256;   // 12288
    const int T2 = EE * NC2 * 192;   // 6144
    int idx = (b - 128) * 256 + tid;
    if (idx < T1) {
        int e = idx / (NC1 * 256);
        int r = idx % (NC1 * 256);
        int chunk = r / 256, n = r % 256;
        const float* src = W1 + ((size_t)e * DD + chunk * 32) * H1C + n;
        uint4* dh = (uint4*)(g_W1h + (size_t)idx * 40);
        #pragma unroll
        for (int q = 0; q < 4; q++) {
            uint32_t ph[4];
            #pragma unroll
            for (int j = 0; j < 4; j++)
                ph[j] = pack2h(src[(size_t)(q * 8 + 2 * j) * H1C],
                               src[(size_t)(q * 8 + 2 * j + 1) * H1C]);
            dh[q] = make_uint4(ph[0], ph[1], ph[2], ph[3]);
        }
        dh[4] = make_uint4(0, 0, 0, 0);
    } else if (idx < T1 + T2) {
        int i2 = idx - T1;
        int e = i2 / (NC2 * 192);
        int r = i2 % (NC2 * 192);
        int chunk = r / 192, n = r % 192;
        const float* src = Wh + ((size_t)e * H1C + chunk * 32) * H2C + n;
        uint4* dh = (uint4*)(g_Whh + (size_t)i2 * 40);
        #pragma unroll
        for (int q = 0; q < 4; q++) {
            uint32_t ph[4];
            #pragma unroll
            for (int j = 0; j < 4; j++)
                ph[j] = pack2h(src[(size_t)(q * 8 + 2 * j) * H2C],
                               src[(size_t)(q * 8 + 2 * j + 1) * H2C]);
            dh[q] = make_uint4(ph[0], ph[1], ph[2], ph[3]);
        }
        dh[4] = make_uint4(0, 0, 0, 0);
    }
}

// ---------------- fused 2-layer MLP + batch reduction (fp16, TM=128) ----------------
__global__ void __launch_bounds__(NT, 1) fused_mlp(
    const float* __restrict__ rep,
    const float* __restrict__ b1, const float* __restrict__ bh,
    const float* __restrict__ W2, const float* __restrict__ b2,
    float* __restrict__ outp)
{
    extern __shared__ __align__(16) char dsm[];
    __shared__ int   prow[TM];
    __shared__ float b1s[H1C];
    __shared__ float bhs[H2C];
    __shared__ float w2s[H2C];
    __shared__ float red[TM][4];
    __shared__ float bins[BB];

    const int tid  = threadIdx.x;
    const int w    = tid >> 5;
    const int lane = tid & 31;
    const int g    = lane >> 2;
    const int t    = lane & 3;
    const int llow = lane & 15;
    const int ahi16 = (lane >> 4) << 4;

    // layer-1 layout: 2 M-slabs x 8 N-strips
    const int wm1 = w >> 3;        // 0..1 -> 64-row slab
    const int wn1 = w & 7;         // 0..7 -> 32-col strip
    // layer-2 layout: 4 M-slabs x 4 N-strips
    const int wm2 = w >> 2;        // 0..3 -> 32-row slab
    const int wn2 = w & 3;         // 0..3 -> 48-col strip

    int c0 = g_counts[0], c1 = g_counts[1], c2 = g_counts[2], c3 = g_counts[3];
    int t0 = (c0 + TM - 1) / TM, t1 = (c1 + TM - 1) / TM;
    int t2 = (c2 + TM - 1) / TM, t3 = (c3 + TM - 1) / TM;
    int bid = blockIdx.x, e, tloc, cnt;
    if      (bid < t0)                { e = 0; tloc = bid;                cnt = c0; }
    else if (bid < t0 + t1)           { e = 1; tloc = bid - t0;           cnt = c1; }
    else if (bid < t0 + t1 + t2)      { e = 2; tloc = bid - t0 - t1;      cnt = c2; }
    else if (bid < t0 + t1 + t2 + t3) { e = 3; tloc = bid - t0 - t1 - t2; cnt = c3; }
    else return;

    const int row0   = tloc * TM;
    const int mcount = min(TM, cnt - row0);
    if (tid < TM)
        prow[tid] = (tid < mcount) ? g_perm[e * NATOMS + row0 + tid] : -1;
    if (tid < H1C) b1s[tid] = b1[e * H1C + tid];
    if (tid < H2C) { bhs[tid] = bh[e * H2C + tid]; w2s[tid] = W2[e * H2C + tid]; }
    if (tid < BB) bins[tid] = 0.f;
    __syncthreads();

    const uint32_t sb = s2u(dsm);
    const char* w1g = (const char*)g_W1h + (size_t)e * NC1 * W1CHUNK;
    const char* whg = (const char*)g_Whh + (size_t)e * NC2 * WHCHUNK;

    // layer-1 fragment offsets
    const uint32_t aoff1 = (uint32_t)((wm1 * 64 + llow) * 80 + ahi16);
    const uint32_t boff1 = (uint32_t)((wn1 * 32 + (lane & 7) + ((lane >> 4) << 3)) * 80
                                      + (((lane >> 3) & 1) << 4));
    // layer-2 fragment offsets
    const uint32_t boff2 = (uint32_t)((wn2 * 48 + (lane & 7) + ((lane >> 4) << 3)) * 80
                                      + (((lane >> 3) & 1) << 4));
    const uint32_t h1row2 = (uint32_t)(wm2 * 32 + llow);
    const uint32_t h1sw2  = (h1row2 & 3) << 4;
    const uint32_t h1off2 = h1row2 * 64;

    // ================== LAYER 1: D1[128x256] = A @ W1[e]^T ==================
    float acc[4][4][4];
    #pragma unroll
    for (int mt = 0; mt < 4; mt++)
        #pragma unroll
        for (int nt = 0; nt < 4; nt++)
            #pragma unroll
            for (int q = 0; q < 4; q++) acc[mt][nt][q] = 0.f;

    float4 va[2];
    // preamble: A(0) -> abuf0, cp.async B(0) -> bbuf0, va = A(1)
    {
        #pragma unroll
        for (int j = 0; j < 2; j++) {
            int item = tid + j * NT;
            int r = item >> 3, f = item & 7;
            int p = prow[r];
            va[j] = (p >= 0) ? __ldg((const float4*)(rep + (size_t)p * DD + f * 4))
                             : make_float4(0.f, 0.f, 0.f, 0.f);
        }
        #pragma unroll 1
        for (int i = tid; i < 1280; i += NT)
            cp16(sb + BBF_OFF + i * 16, w1g + i * 16);
        cp_commit();
        char* Ah = dsm + AB_OFF;
        #pragma unroll
        for (int j = 0; j < 2; j++) {
            int item = tid + j * NT;
            int r = item >> 3, f = item & 7;
            *(uint2*)(Ah + r * 80 + f * 8) =
                make_uint2(pack2h(va[j].x, va[j].y), pack2h(va[j].z, va[j].w));
        }
        #pragma unroll
        for (int j = 0; j < 2; j++) {
            int item = tid + j * NT;
            int r = item >> 3, f = item & 7;
            int p = prow[r];
            va[j] = (p >= 0) ? __ldg((const float4*)(rep + (size_t)p * DD + 32 + f * 4))
                             : make_float4(0.f, 0.f, 0.f, 0.f);
        }
        cp_wait0();
        __syncthreads();
    }

    for (int kc = 0; kc < NC1; kc++) {
        const int buf = kc & 1;
        if (kc + 1 < NC1) {
            const int nb = buf ^ 1;
            const char* srcH = w1g + (size_t)(kc + 1) * W1CHUNK;
            #pragma unroll 1
            for (int i = tid; i < 1280; i += NT)
                cp16(sb + BBF_OFF + nb * BBF_BUF + i * 16, srcH + i * 16);
            cp_commit();
        }
        // MMA chunk kc: 6 ldm4 feed 16 MMAs per kk
        {
            const uint32_t aB = sb + AB_OFF + buf * AB_BUF + aoff1;
            const uint32_t bB = sb + BBF_OFF + buf * BBF_BUF + boff1;
            #pragma unroll
            for (int kk = 0; kk < 2; kk++) {
                const uint32_t kb2 = kk * 32;
                uint32_t af[4][4];
                uint32_t bf[2][4];
                ldm4(af[0], aB + kb2);
                ldm4(af[1], aB + 1280 + kb2);
                ldm4(af[2], aB + 2560 + kb2);
                ldm4(af[3], aB + 3840 + kb2);
                ldm4(bf[0], bB + kb2);
                ldm4(bf[1], bB + 1280 + kb2);
                #pragma unroll
                for (int nh = 0; nh < 2; nh++) {
                    #pragma unroll
                    for (int mt = 0; mt < 4; mt++) {
                        mma_f16(acc[mt][2 * nh],     af[mt], bf[nh][0], bf[nh][1]);
                        mma_f16(acc[mt][2 * nh + 1], af[mt], bf[nh][2], bf[nh][3]);
                    }
                }
            }
        }
        if (kc + 1 < NC1) {
            char* Ah = dsm + AB_OFF + (buf ^ 1) * AB_BUF;
            #pragma unroll
            for (int j = 0; j < 2; j++) {
                int item = tid + j * NT;
                int r = item >> 3, f = item & 7;
                *(uint2*)(Ah + r * 80 + f * 8) =
                    make_uint2(pack2h(va[j].x, va[j].y), pack2h(va[j].z, va[j].w));
            }
            if (kc + 2 < NC1) {
                #pragma unroll
                for (int j = 0; j < 2; j++) {
                    int item = tid + j * NT;
                    int r = item >> 3, f = item & 7;
                    int p = prow[r];
                    va[j] = (p >= 0)
                          ? __ldg((const float4*)(rep + (size_t)p * DD + (kc + 2) * 32 + f * 4))
                          : make_float4(0.f, 0.f, 0.f, 0.f);
                }
            }
            cp_wait0();
        }
        __syncthreads();
    }

    // ---- prefetch Wh chunk 0 (WB disjoint from H1) ----
    {
        #pragma unroll 1
        for (int i = tid; i < 960; i += NT)
            cp16(sb + WB_OFF + i * 16, whg + i * 16);
        cp_commit();
    }

    // ---- H1 = D1 + b1 (NO relu — reference quirk) -> chunked swizzled smem ----
    {
        char* Hh = dsm + H1_OFF;
        #pragma unroll
        for (int mt = 0; mt < 4; mt++) {
            #pragma unroll
            for (int nt = 0; nt < 4; nt++) {
                int kin = nt * 8 + 2 * t;
                int c0i = wn1 * 32 + kin;
                int r0 = wm1 * 64 + mt * 16 + g, r1 = r0 + 8;
                uint32_t o0 = wn1 * H1_CHK + r0 * 64 + ((kin * 2) ^ ((r0 & 3) << 4));
                *(uint32_t*)(Hh + o0) =
                    pack2h(acc[mt][nt][0] + b1s[c0i], acc[mt][nt][1] + b1s[c0i + 1]);
                uint32_t o1 = wn1 * H1_CHK + r1 * 64 + ((kin * 2) ^ ((r1 & 3) << 4));
                *(uint32_t*)(Hh + o1) =
                    pack2h(acc[mt][nt][2] + b1s[c0i], acc[mt][nt][3] + b1s[c0i + 1]);
            }
        }
    }
    cp_wait0();
    __syncthreads();

    // ================== LAYER 2: D2[128x192] = H1 @ Wh[e]^T ==================
    float acc2[2][6][4];
    #pragma unroll
    for (int mt = 0; mt < 2; mt++)
        #pragma unroll
        for (int nt = 0; nt < 6; nt++)
            #pragma unroll
            for (int q = 0; q < 4; q++) acc2[mt][nt][q] = 0.f;

    for (int kc = 0; kc < NC2; kc++) {
        const int buf = kc & 1;
        if (kc + 1 < NC2) {
            const char* srcH = whg + (size_t)(kc + 1) * WHCHUNK;
            #pragma unroll 1
            for (int i = tid; i < 960; i += NT)
                cp16(sb + WB_OFF + (buf ^ 1) * WB_BUF + i * 16, srcH + i * 16);
            cp_commit();
        }
        {
            const uint32_t bB = sb + WB_OFF + buf * WB_BUF + boff2;
            const uint32_t aH = sb + H1_OFF + kc * H1_CHK;
            #pragma unroll
            for (int kk = 0; kk < 2; kk++) {
                const uint32_t kb2 = kk * 32;
                const uint32_t colsw = (kb2 + ahi16) ^ h1sw2;
                uint32_t ah0[4], ah1[4];
                uint32_t bf[3][4];
                ldm4(ah0, aH + h1off2 + colsw);
                ldm4(ah1, aH + h1off2 + 1024 + colsw);
                ldm4(bf[0], bB + kb2);
                ldm4(bf[1], bB + 1280 + kb2);
                ldm4(bf[2], bB + 2560 + kb2);
                #pragma unroll
                for (int pg = 0; pg < 3; pg++) {
                    mma_f16(acc2[0][2 * pg],     ah0, bf[pg][0], bf[pg][1]);
                    mma_f16(acc2[1][2 * pg],     ah1, bf[pg][0], bf[pg][1]);
                    mma_f16(acc2[0][2 * pg + 1], ah0, bf[pg][2], bf[pg][3]);
                    mma_f16(acc2[1][2 * pg + 1], ah1, bf[pg][2], bf[pg][3]);
                }
            }
        }
        if (kc + 1 < NC2) cp_wait0();
        __syncthreads();
    }

    // ---- fused epilogue: E = relu(D2 + bh) . W2 + b2, per-batch bins ----
    {
        const int C0 = wn2 * 48;
        const int R0 = wm2 * 32;
        float pv[2][2] = {{0.f, 0.f}, {0.f, 0.f}};
        #pragma unroll
        for (int mt = 0; mt < 2; mt++) {
            #pragma unroll
            for (int nt = 0; nt < 6; nt++) {
                int c0i = C0 + nt * 8 + 2 * t;
                float bb0 = bhs[c0i],     w0 = w2s[c0i];
                float bb1 = bhs[c0i + 1], w1v = w2s[c0i + 1];
                float v;
                v = acc2[mt][nt][0] + bb0; v = v > 0.f ? v : 0.f; pv[mt][0] = fmaf(v, w0,  pv[mt][0]);
                v = acc2[mt][nt][1] + bb1; v = v > 0.f ? v : 0.f; pv[mt][0] = fmaf(v, w1v, pv[mt][0]);
                v = acc2[mt][nt][2] + bb0; v = v > 0.f ? v : 0.f; pv[mt][1] = fmaf(v, w0,  pv[mt][1]);
                v = acc2[mt][nt][3] + bb1; v = v > 0.f ? v : 0.f; pv[mt][1] = fmaf(v, w1v, pv[mt][1]);
            }
        }
        #pragma unroll
        for (int mt = 0; mt < 2; mt++) {
            #pragma unroll
            for (int h = 0; h < 2; h++) {
                pv[mt][h] += __shfl_xor_sync(0xffffffffu, pv[mt][h], 1);
                pv[mt][h] += __shfl_xor_sync(0xffffffffu, pv[mt][h], 2);
            }
        }
        if (t == 0) {
            #pragma unroll
            for (int mt = 0; mt < 2; mt++) {
                red[R0 + mt * 16 + g][wn2]     = pv[mt][0];
                red[R0 + mt * 16 + 8 + g][wn2] = pv[mt][1];
            }
        }
        __syncthreads();
        if (tid < TM) {
            int pr = prow[tid];
            if (pr >= 0) {
                float en = red[tid][0] + red[tid][1] + red[tid][2] + red[tid][3] + b2[e];
                atomicAdd(&bins[pr >> 10], en);
            }
        }
        __syncthreads();
        if (tid < BB) {
            float v = bins[tid];
            if (v != 0.f) atomicAdd(&outp[tid], v);
        }
    }
}

extern "C" void kernel_launch(void* const* d_in, const int* in_sizes, int n_in,
                              void* d_out, int out_size) {
    const float* rep     = (const float*)d_in[0];
    const int*   species = (const int*)  d_in[1];
    const float* W1      = (const float*)d_in[2];
    const float* b1      = (const float*)d_in[3];
    const float* Wh      = (const float*)d_in[4];
    const float* bh      = (const float*)d_in[5];
    const float* W2      = (const float*)d_in[6];
    const float* b2      = (const float*)d_in[7];
    float* out = (float*)d_out;

    cudaFuncSetAttribute(fused_mlp,
                         cudaFuncAttributeMaxDynamicSharedMemorySize, DSMEM);

    zero_kernel<<<1, 32>>>(out);
    bucket_prep_kernel<<<200, 256>>>(species, W1, Wh);
    fused_mlp<<<MAXTILES, NT, DSMEM>>>(rep, b1, bh, W2, b2, out);
}